// round 10
// baseline (speedup 1.0000x reference)
#include <cuda_runtime.h>
#include <cuda_bf16.h>
#include <cstdint>
#include <math.h>

// ---------------------------------------------------------------------------
// Problem constants
// ---------------------------------------------------------------------------
#define BB   2
#define SS   2048
#define DD   2048
#define HH   16
#define DK   128
#define MTOK (BB * SS)          // 4096 tokens
#define SCALE 0.08838834764831845f  // 1/sqrt(128)

// Scratch (device globals; no cudaMalloc allowed)
static __device__ float g_v [(size_t)MTOK * DD];
static __device__ float g_rpart[(size_t)BB * HH * SS * 16];
static __device__ float g_inv[(size_t)BB * HH * SS];
// bf16 hi/lo planes
static __device__ __nv_bfloat16 g_qih[(size_t)MTOK * DD], g_qil[(size_t)MTOK * DD];
static __device__ __nv_bfloat16 g_kih[(size_t)MTOK * DD], g_kil[(size_t)MTOK * DD];
static __device__ __nv_bfloat16 g_vih[(size_t)MTOK * DD], g_vil[(size_t)MTOK * DD];
static __device__ __nv_bfloat16 g_wh[(size_t)4 * DD * DD], g_wl[(size_t)4 * DD * DD];
static __device__ __nv_bfloat16 g_qh[(size_t)MTOK * DD], g_ql[(size_t)MTOK * DD];
static __device__ __nv_bfloat16 g_kh[(size_t)MTOK * DD], g_kl[(size_t)MTOK * DD];
static __device__ __nv_bfloat16 g_xh[(size_t)MTOK * DD], g_xl[(size_t)MTOK * DD];
static __device__ __nv_bfloat16 g_vth[(size_t)BB * HH * DK * SS];
static __device__ __nv_bfloat16 g_vtl[(size_t)BB * HH * DK * SS];
// Unnormalized-E planes
static __device__ __nv_bfloat16 g_eh[(size_t)BB * HH * SS * SS];
static __device__ __nv_bfloat16 g_el[(size_t)BB * HH * SS * SS];

// ---------------------------------------------------------------------------
// PTX helpers
// ---------------------------------------------------------------------------
#define LDSM_X4(r0, r1, r2, r3, addr) \
    asm volatile("ldmatrix.sync.aligned.m8n8.x4.shared.b16 {%0,%1,%2,%3}, [%4];" \
        : "=r"(r0), "=r"(r1), "=r"(r2), "=r"(r3) : "r"(addr))

#define MMA16816(c, a0, a1, a2, a3, b0, b1) \
    asm volatile("mma.sync.aligned.m16n8k16.row.col.f32.bf16.bf16.f32 " \
        "{%0,%1,%2,%3}, {%4,%5,%6,%7}, {%8,%9}, {%0,%1,%2,%3};" \
        : "+f"((c)[0]), "+f"((c)[1]), "+f"((c)[2]), "+f"((c)[3]) \
        : "r"(a0), "r"(a1), "r"(a2), "r"(a3), "r"(b0), "r"(b1))

#define CP16(dst, src) \
    asm volatile("cp.async.cg.shared.global [%0], [%1], 16;" \
        :: "r"(dst), "l"(src))
#define CPCOMMIT() asm volatile("cp.async.commit_group;" ::: "memory")
#define CPWAIT1()  asm volatile("cp.async.wait_group 1;" ::: "memory")

__device__ __forceinline__ uint32_t smem_u32(const void* p) {
    uint32_t a;
    asm("{ .reg .u64 t; cvta.to.shared.u64 t, %1; cvt.u32.u64 %0, t; }"
        : "=r"(a) : "l"(p));
    return a;
}

__device__ __forceinline__ uint32_t pack_bf2(__nv_bfloat16 a, __nv_bfloat16 b) {
    return (uint32_t)__bfloat16_as_ushort(a) |
           ((uint32_t)__bfloat16_as_ushort(b) << 16);
}

__device__ __forceinline__ void split4(const float4 f, uint2& hi, uint2& lo) {
    __nv_bfloat16 h0 = __float2bfloat16_rn(f.x);
    __nv_bfloat16 h1 = __float2bfloat16_rn(f.y);
    __nv_bfloat16 h2 = __float2bfloat16_rn(f.z);
    __nv_bfloat16 h3 = __float2bfloat16_rn(f.w);
    __nv_bfloat16 l0 = __float2bfloat16_rn(f.x - __bfloat162float(h0));
    __nv_bfloat16 l1 = __float2bfloat16_rn(f.y - __bfloat162float(h1));
    __nv_bfloat16 l2 = __float2bfloat16_rn(f.z - __bfloat162float(h2));
    __nv_bfloat16 l3 = __float2bfloat16_rn(f.w - __bfloat162float(h3));
    hi.x = pack_bf2(h0, h1); hi.y = pack_bf2(h2, h3);
    lo.x = pack_bf2(l0, l1); lo.y = pack_bf2(l2, l3);
}

// ---------------------------------------------------------------------------
// MmaB16v3: 128x128 tile, K-chunk 16, 3-stage cp.async pipeline,
// 3 CTAs/SM (73.7KB smem, <=84 regs via launch bounds).
// ---------------------------------------------------------------------------
#define NS 3
#define RS2 48
#define ST_AHI 0
#define ST_ALO 6144
#define ST_BHI 12288
#define ST_BLO 18432
#define ST_BYTES 24576
#define DSMEM_TOTAL (NS * ST_BYTES)   // 73728

struct MmaB16v3 {
    float acc[4][4][4];

    __device__ __forceinline__ static void issue(
        uint32_t sb,
        const __nv_bfloat16* Ah, const __nv_bfloat16* Al, size_t sA,
        const __nv_bfloat16* Bh, const __nv_bfloat16* Bl, size_t sB,
        int k0, int tid)
    {
        const int row  = tid >> 1;
        const int half = tid & 1;
        const uint32_t so = (uint32_t)row * RS2 + half * 16;
        const size_t oA = (size_t)row * sA + k0 + half * 8;
        const size_t oB = (size_t)row * sB + k0 + half * 8;
        CP16(sb + ST_AHI + so, Ah + oA);
        CP16(sb + ST_ALO + so, Al + oA);
        CP16(sb + ST_BHI + so, Bh + oB);
        CP16(sb + ST_BLO + so, Bl + oB);
    }

    __device__ __forceinline__ void run(
        uint32_t sbase,
        const __nv_bfloat16* Ah, const __nv_bfloat16* Al, size_t sA,
        const __nv_bfloat16* Bh, const __nv_bfloat16* Bl, size_t sB,
        const int nIter, const int tid)
    {
        const int lane = tid & 31;
        const int wid  = tid >> 5;
        const int wm   = wid >> 2;
        const int wn   = wid & 3;

        #pragma unroll
        for (int i = 0; i < 4; i++)
            #pragma unroll
            for (int j = 0; j < 4; j++)
                #pragma unroll
                for (int c = 0; c < 4; c++) acc[i][j][c] = 0.0f;

        const uint32_t aAddr = sbase + ST_AHI
            + (uint32_t)(wm * 64 + (lane & 15)) * RS2 + (lane >> 4) * 16;
        const uint32_t bAddr = sbase + ST_BHI
            + (uint32_t)(wn * 32 + (lane & 7) + ((lane >> 4) & 1) * 8) * RS2
            + ((lane >> 3) & 1) * 16;

        // Prologue: stages 0,1 into buffers 0,1
        #pragma unroll
        for (int p = 0; p < NS - 1; p++) {
            if (p < nIter)
                issue(sbase + p * ST_BYTES, Ah, Al, sA, Bh, Bl, sB, p * 16, tid);
            CPCOMMIT();
        }

        int bufc = 0;               // compute buffer for stage s
        int bufi = NS - 1;          // issue buffer for stage s+2
        for (int s = 0; s < nIter; s++) {
            CPWAIT1();
            __syncthreads();

            const uint32_t bo = (uint32_t)bufc * ST_BYTES;
            uint32_t ahi[4][4], alo[4][4];
            uint32_t bhi[2][4], blo[2][4];
            #pragma unroll
            for (int mt = 0; mt < 4; mt++) {
                const uint32_t a = aAddr + bo + mt * (16 * RS2);
                LDSM_X4(ahi[mt][0], ahi[mt][1], ahi[mt][2], ahi[mt][3], a);
                LDSM_X4(alo[mt][0], alo[mt][1], alo[mt][2], alo[mt][3],
                        a + (ST_ALO - ST_AHI));
            }
            #pragma unroll
            for (int pp = 0; pp < 2; pp++) {
                const uint32_t b = bAddr + bo + pp * (16 * RS2);
                LDSM_X4(bhi[pp][0], bhi[pp][1], bhi[pp][2], bhi[pp][3], b);
                LDSM_X4(blo[pp][0], blo[pp][1], blo[pp][2], blo[pp][3],
                        b + (ST_BLO - ST_BHI));
            }
            #pragma unroll
            for (int mt = 0; mt < 4; mt++) {
                #pragma unroll
                for (int pp = 0; pp < 2; pp++) {
                    #pragma unroll
                    for (int t = 0; t < 2; t++) {
                        const int nt = pp * 2 + t;
                        MMA16816(acc[mt][nt],
                                 ahi[mt][0], ahi[mt][1], ahi[mt][2], ahi[mt][3],
                                 bhi[pp][t * 2], bhi[pp][t * 2 + 1]);
                        MMA16816(acc[mt][nt],
                                 ahi[mt][0], ahi[mt][1], ahi[mt][2], ahi[mt][3],
                                 blo[pp][t * 2], blo[pp][t * 2 + 1]);
                        MMA16816(acc[mt][nt],
                                 alo[mt][0], alo[mt][1], alo[mt][2], alo[mt][3],
                                 bhi[pp][t * 2], bhi[pp][t * 2 + 1]);
                    }
                }
            }

            const int nx = s + NS - 1;
            if (nx < nIter)
                issue(sbase + (uint32_t)bufi * ST_BYTES,
                      Ah, Al, sA, Bh, Bl, sB, nx * 16, tid);
            CPCOMMIT();

            bufc = (bufc + 1 == NS) ? 0 : bufc + 1;
            bufi = (bufi + 1 == NS) ? 0 : bufi + 1;
        }
        __syncthreads();
    }
};

// ---------------------------------------------------------------------------
// Split fp32 tensors into bf16 hi/lo planes
// ---------------------------------------------------------------------------
__global__ __launch_bounds__(256) void split_inputs(
    const float* __restrict__ a0, const float* __restrict__ a1,
    const float* __restrict__ a2,
    __nv_bfloat16* __restrict__ h0, __nv_bfloat16* __restrict__ l0,
    __nv_bfloat16* __restrict__ h1, __nv_bfloat16* __restrict__ l1,
    __nv_bfloat16* __restrict__ h2, __nv_bfloat16* __restrict__ l2)
{
    const int z = blockIdx.y;
    const float* s = (z == 0) ? a0 : (z == 1) ? a1 : a2;
    __nv_bfloat16* H = (z == 0) ? h0 : (z == 1) ? h1 : h2;
    __nv_bfloat16* L = (z == 0) ? l0 : (z == 1) ? l1 : l2;
    const size_t i = ((size_t)blockIdx.x * 256 + threadIdx.x) * 4;
    float4 f = *(const float4*)(s + i);
    uint2 hi, lo;
    split4(f, hi, lo);
    *(uint2*)(H + i) = hi;
    *(uint2*)(L + i) = lo;
}

__global__ __launch_bounds__(256) void split_weights(
    const float* __restrict__ w0, const float* __restrict__ w1,
    const float* __restrict__ w2, const float* __restrict__ w3,
    __nv_bfloat16* __restrict__ wh, __nv_bfloat16* __restrict__ wl)
{
    const int z = blockIdx.y;
    const float* s = (z == 0) ? w0 : (z == 1) ? w1 : (z == 2) ? w2 : w3;
    const size_t base = (size_t)z * DD * DD;
    const size_t i = ((size_t)blockIdx.x * 256 + threadIdx.x) * 4;
    float4 f = *(const float4*)(s + i);
    uint2 hi, lo;
    split4(f, hi, lo);
    *(uint2*)(wh + base + i) = hi;
    *(uint2*)(wl + base + i) = lo;
}

// ---------------------------------------------------------------------------
// Batched Q/K/V projection: z=0 -> q planes, z=1 -> k planes, z=2 -> v fp32
// ---------------------------------------------------------------------------
__global__ __launch_bounds__(256, 3) void proj_qkv(
    const __nv_bfloat16* __restrict__ qih, const __nv_bfloat16* __restrict__ qil,
    const __nv_bfloat16* __restrict__ kih, const __nv_bfloat16* __restrict__ kil,
    const __nv_bfloat16* __restrict__ vih, const __nv_bfloat16* __restrict__ vil,
    const __nv_bfloat16* __restrict__ wh, const __nv_bfloat16* __restrict__ wl,
    const float* __restrict__ bq, const float* __restrict__ bk,
    const float* __restrict__ bv,
    __nv_bfloat16* __restrict__ qh, __nv_bfloat16* __restrict__ ql,
    __nv_bfloat16* __restrict__ kh, __nv_bfloat16* __restrict__ kl,
    float* __restrict__ v)
{
    extern __shared__ char dsm[];
    const uint32_t sbase = smem_u32(dsm);
    const int tid  = threadIdx.x;
    const int lane = tid & 31;
    const int wid  = tid >> 5;
    const int wm   = wid >> 2;
    const int wn   = wid & 3;
    const int bn   = blockIdx.x;
    const int bm   = blockIdx.y;
    const int z    = blockIdx.z;

    const __nv_bfloat16* Ah = (z == 0) ? qih : (z == 1) ? kih : vih;
    const __nv_bfloat16* Al = (z == 0) ? qil : (z == 1) ? kil : vil;
    const float* bias = (z == 0) ? bq : (z == 1) ? bk : bv;
    const size_t wbase = (size_t)z * DD * DD;

    MmaB16v3 core;
    core.run(sbase,
             Ah + (size_t)(bm * 128) * DD, Al + (size_t)(bm * 128) * DD, DD,
             wh + wbase + (size_t)(bn * 128) * DD,
             wl + wbase + (size_t)(bn * 128) * DD, DD,
             DD / 16, tid);

    #pragma unroll
    for (int mt = 0; mt < 4; mt++) {
        const int row = bm * 128 + wm * 64 + mt * 16 + (lane >> 2);
        #pragma unroll
        for (int nt = 0; nt < 4; nt++) {
            const int col = bn * 128 + wn * 32 + nt * 8 + (lane & 3) * 2;
            const float b0 = bias[col], b1 = bias[col + 1];
            const float v0 = core.acc[mt][nt][0] + b0;
            const float v1 = core.acc[mt][nt][1] + b1;
            const float v2 = core.acc[mt][nt][2] + b0;
            const float v3 = core.acc[mt][nt][3] + b1;
            if (z == 2) {
                *(float2*)(v + (size_t)row * DD + col) = make_float2(v0, v1);
                *(float2*)(v + (size_t)(row + 8) * DD + col) = make_float2(v2, v3);
            } else {
                __nv_bfloat16* H = (z == 0) ? qh : kh;
                __nv_bfloat16* L = (z == 0) ? ql : kl;
                __nv_bfloat16 h0 = __float2bfloat16_rn(v0);
                __nv_bfloat16 h1 = __float2bfloat16_rn(v1);
                __nv_bfloat16 h2 = __float2bfloat16_rn(v2);
                __nv_bfloat16 h3 = __float2bfloat16_rn(v3);
                *(uint32_t*)(H + (size_t)row * DD + col) = pack_bf2(h0, h1);
                *(uint32_t*)(L + (size_t)row * DD + col) = pack_bf2(
                    __float2bfloat16_rn(v0 - __bfloat162float(h0)),
                    __float2bfloat16_rn(v1 - __bfloat162float(h1)));
                *(uint32_t*)(H + (size_t)(row + 8) * DD + col) = pack_bf2(h2, h3);
                *(uint32_t*)(L + (size_t)(row + 8) * DD + col) = pack_bf2(
                    __float2bfloat16_rn(v2 - __bfloat162float(h2)),
                    __float2bfloat16_rn(v3 - __bfloat162float(h3)));
            }
        }
    }
}

// ---------------------------------------------------------------------------
// Final GEMM: out = x @ Wo^T + bo
// ---------------------------------------------------------------------------
__global__ __launch_bounds__(256, 3) void gemm_b16(
    const __nv_bfloat16* __restrict__ Ah, const __nv_bfloat16* __restrict__ Al,
    const __nv_bfloat16* __restrict__ Wh, const __nv_bfloat16* __restrict__ Wl,
    const float* __restrict__ bias, float* __restrict__ C)
{
    extern __shared__ char dsm[];
    const uint32_t sbase = smem_u32(dsm);
    const int tid  = threadIdx.x;
    const int lane = tid & 31;
    const int wid  = tid >> 5;
    const int wm   = wid >> 2;
    const int wn   = wid & 3;
    const int bn   = blockIdx.x;
    const int bm   = blockIdx.y;

    MmaB16v3 core;
    core.run(sbase,
             Ah + (size_t)(bm * 128) * DD, Al + (size_t)(bm * 128) * DD, DD,
             Wh + (size_t)(bn * 128) * DD, Wl + (size_t)(bn * 128) * DD, DD,
             DD / 16, tid);

    #pragma unroll
    for (int mt = 0; mt < 4; mt++) {
        const int row = bm * 128 + wm * 64 + mt * 16 + (lane >> 2);
        #pragma unroll
        for (int nt = 0; nt < 4; nt++) {
            const int col = bn * 128 + wn * 32 + nt * 8 + (lane & 3) * 2;
            const float b0 = bias[col], b1 = bias[col + 1];
            float2 o0, o1;
            o0.x = core.acc[mt][nt][0] + b0; o0.y = core.acc[mt][nt][1] + b1;
            o1.x = core.acc[mt][nt][2] + b0; o1.y = core.acc[mt][nt][3] + b1;
            *(float2*)(C + (size_t)row * DD + col) = o0;
            *(float2*)(C + (size_t)(row + 8) * DD + col) = o1;
        }
    }
}

// ---------------------------------------------------------------------------
// Scores+exp: triangular grid (136 lower tiles per bh). Writes unnormalized
// E planes (bf16 hi/lo) + per-tile row-sum partials.
// ---------------------------------------------------------------------------
__global__ __launch_bounds__(256, 3) void scores_exp_kernel(
    const __nv_bfloat16* __restrict__ qh, const __nv_bfloat16* __restrict__ ql,
    const __nv_bfloat16* __restrict__ kh, const __nv_bfloat16* __restrict__ kl,
    __nv_bfloat16* __restrict__ eh, __nv_bfloat16* __restrict__ el,
    float* __restrict__ rpart)
{
    const int idx = blockIdx.x;            // 0..135 (lower-triangle tile id)
    int bm = (int)((sqrtf(8.f * idx + 1.f) - 1.f) * 0.5f);
    while ((bm + 1) * (bm + 2) / 2 <= idx) bm++;
    while (bm * (bm + 1) / 2 > idx) bm--;
    const int bn = idx - bm * (bm + 1) / 2;
    const int bh = blockIdx.y;
    const int tid = threadIdx.x;

    extern __shared__ char dsm[];
    __shared__ float rs[128][4];
    const uint32_t sbase = smem_u32(dsm);
    const int lane = tid & 31;
    const int wid  = tid >> 5;
    const int wm   = wid >> 2;
    const int wn   = wid & 3;
    const int b = bh / HH, h = bh % HH;

    const size_t aoff = (size_t)(b * SS + bm * 128) * DD + h * DK;
    const size_t boff = (size_t)(b * SS + bn * 128) * DD + h * DK;

    MmaB16v3 core;
    core.run(sbase, qh + aoff, ql + aoff, DD, kh + boff, kl + boff, DD,
             DK / 16, tid);

    __nv_bfloat16* peh = eh + (size_t)bh * SS * SS;
    __nv_bfloat16* pel = el + (size_t)bh * SS * SS;

    float rsum[4][2];
    #pragma unroll
    for (int mt = 0; mt < 4; mt++) { rsum[mt][0] = 0.f; rsum[mt][1] = 0.f; }

    #pragma unroll
    for (int mt = 0; mt < 4; mt++) {
        const int r0 = bm * 128 + wm * 64 + mt * 16 + (lane >> 2);
        const int r1 = r0 + 8;
        #pragma unroll
        for (int nt = 0; nt < 4; nt++) {
            const int col = bn * 128 + wn * 32 + nt * 8 + (lane & 3) * 2;
            float e0 = (col     <= r0) ? __expf(core.acc[mt][nt][0] * SCALE) : 0.f;
            float e1 = (col + 1 <= r0) ? __expf(core.acc[mt][nt][1] * SCALE) : 0.f;
            float e2 = (col     <= r1) ? __expf(core.acc[mt][nt][2] * SCALE) : 0.f;
            float e3 = (col + 1 <= r1) ? __expf(core.acc[mt][nt][3] * SCALE) : 0.f;
            rsum[mt][0] += e0 + e1;
            rsum[mt][1] += e2 + e3;
            __nv_bfloat16 h0 = __float2bfloat16_rn(e0);
            __nv_bfloat16 h1 = __float2bfloat16_rn(e1);
            __nv_bfloat16 h2 = __float2bfloat16_rn(e2);
            __nv_bfloat16 h3 = __float2bfloat16_rn(e3);
            *(uint32_t*)(peh + (size_t)r0 * SS + col) = pack_bf2(h0, h1);
            *(uint32_t*)(pel + (size_t)r0 * SS + col) = pack_bf2(
                __float2bfloat16_rn(e0 - __bfloat162float(h0)),
                __float2bfloat16_rn(e1 - __bfloat162float(h1)));
            *(uint32_t*)(peh + (size_t)r1 * SS + col) = pack_bf2(h2, h3);
            *(uint32_t*)(pel + (size_t)r1 * SS + col) = pack_bf2(
                __float2bfloat16_rn(e2 - __bfloat162float(h2)),
                __float2bfloat16_rn(e3 - __bfloat162float(h3)));
        }
    }

    #pragma unroll
    for (int mt = 0; mt < 4; mt++) {
        #pragma unroll
        for (int hf = 0; hf < 2; hf++) {
            float vv = rsum[mt][hf];
            vv += __shfl_xor_sync(0xffffffffu, vv, 1);
            vv += __shfl_xor_sync(0xffffffffu, vv, 2);
            if ((lane & 3) == 0) {
                const int lrow = wm * 64 + mt * 16 + hf * 8 + (lane >> 2);
                rs[lrow][wn] = vv;
            }
        }
    }
    __syncthreads();
    if (tid < 128) {
        const float p = rs[tid][0] + rs[tid][1] + rs[tid][2] + rs[tid][3];
        rpart[((size_t)bh * SS + bm * 128 + tid) * 16 + bn] = p;
    }
}

// ---------------------------------------------------------------------------
// ginv: 1/rowsum from partials
// ---------------------------------------------------------------------------
__global__ __launch_bounds__(256) void ginv_kernel(
    const float* __restrict__ rpart, float* __restrict__ ginv)
{
    const int i = blockIdx.x * 256 + threadIdx.x;   // bh*SS + s
    const int s = i & (SS - 1);
    const float* p = rpart + (size_t)i * 16;
    const int nb = (s >> 7) + 1;
    float sum = 0.f;
    for (int k = 0; k < nb; k++) sum += p[k];
    ginv[i] = 1.0f / sum;
}

// ---------------------------------------------------------------------------
// Zero the above-diagonal tail of attn (side stream)
// ---------------------------------------------------------------------------
__global__ __launch_bounds__(256) void zero_tail(float* __restrict__ attn)
{
    const int blk = blockIdx.x;           // bh*SS + s
    const int s   = blk & (SS - 1);
    const int limit = ((s >> 7) + 1) * 128;
    float* row = attn + (size_t)blk * SS;
    const float4 z = make_float4(0.f, 0.f, 0.f, 0.f);
    for (int j = limit + threadIdx.x * 4; j < SS; j += 1024)
        *(float4*)(row + j) = z;
}

// ---------------------------------------------------------------------------
// Finalize (prefix only): attn[0..limit) = (Eh+El)*inv. Tail pre-zeroed.
// ---------------------------------------------------------------------------
__global__ __launch_bounds__(256) void finalize_prefix(
    const __nv_bfloat16* __restrict__ eh, const __nv_bfloat16* __restrict__ el,
    const float* __restrict__ ginv, float* __restrict__ attn)
{
    const int blk = blockIdx.x;           // bh*SS + s
    const int s   = blk & (SS - 1);
    const float inv = ginv[blk];
    const __nv_bfloat16* reh = eh + (size_t)blk * SS;
    const __nv_bfloat16* rel = el + (size_t)blk * SS;
    float* row = attn + (size_t)blk * SS;
    const int limit = ((s >> 7) + 1) * 128;
    for (int j = threadIdx.x * 4; j < limit; j += 1024) {
        const __nv_bfloat162 h2 = *(const __nv_bfloat162*)(reh + j);
        const __nv_bfloat162 h3 = *(const __nv_bfloat162*)(reh + j + 2);
        const __nv_bfloat162 l2 = *(const __nv_bfloat162*)(rel + j);
        const __nv_bfloat162 l3 = *(const __nv_bfloat162*)(rel + j + 2);
        float4 o;
        o.x = (__bfloat162float(h2.x) + __bfloat162float(l2.x)) * inv;
        o.y = (__bfloat162float(h2.y) + __bfloat162float(l2.y)) * inv;
        o.z = (__bfloat162float(h3.x) + __bfloat162float(l3.x)) * inv;
        o.w = (__bfloat162float(h3.y) + __bfloat162float(l3.y)) * inv;
        *(float4*)(row + j) = o;
    }
}

// ---------------------------------------------------------------------------
// Transpose V per head into bf16 hi/lo planes: vt[bh][d][s]
// ---------------------------------------------------------------------------
__global__ __launch_bounds__(256) void transpose_v(
    const float* __restrict__ v,
    __nv_bfloat16* __restrict__ vth, __nv_bfloat16* __restrict__ vtl)
{
    __shared__ float t[32][33];
    const int bh = blockIdx.z, b = bh / HH, h = bh % HH;
    const int s0 = blockIdx.x * 32, d0 = blockIdx.y * 32;
    const int tx = threadIdx.x & 31, ty = threadIdx.x >> 5;
    #pragma unroll
    for (int i = 0; i < 4; i++)
        t[ty + i * 8][tx] =
            v[(size_t)(b * SS + s0 + ty + i * 8) * DD + h * DK + d0 + tx];
    __syncthreads();
    #pragma unroll
    for (int i = 0; i < 4; i++) {
        const float f = t[tx][ty + i * 8];
        const __nv_bfloat16 hh = __float2bfloat16_rn(f);
        const __nv_bfloat16 ll = __float2bfloat16_rn(f - __bfloat162float(hh));
        const size_t idx = (size_t)bh * DK * SS + (size_t)(d0 + ty + i * 8) * SS
                         + s0 + tx;
        vth[idx] = hh;
        vtl[idx] = ll;
    }
}

// ---------------------------------------------------------------------------
// AV: x = (E @ V) * inv from unnormalized E planes; heavy-first 1D grid.
// ---------------------------------------------------------------------------
__global__ __launch_bounds__(256, 3) void av_mma_kernel(
    const __nv_bfloat16* __restrict__ eh, const __nv_bfloat16* __restrict__ el,
    const __nv_bfloat16* __restrict__ vth, const __nv_bfloat16* __restrict__ vtl,
    const float* __restrict__ ginv,
    __nv_bfloat16* __restrict__ xh, __nv_bfloat16* __restrict__ xl)
{
    const int t = blockIdx.x;              // 0..511, heavy bm first
    const int bm = 15 - (t >> 5);
    const int bh = t & 31;
    extern __shared__ char dsm[];
    const uint32_t sbase = smem_u32(dsm);
    const int b = bh / HH, h = bh % HH;
    const int tid  = threadIdx.x;
    const int lane = tid & 31;
    const int wid  = tid >> 5;
    const int wm   = wid >> 2;
    const int wn   = wid & 3;

    const size_t aoff = (size_t)bh * SS * SS + (size_t)(bm * 128) * SS;
    const size_t boff = (size_t)bh * DK * SS;

    MmaB16v3 core;
    core.run(sbase, eh + aoff, el + aoff, SS, vth + boff, vtl + boff, SS,
             (bm + 1) * 8, tid);

    #pragma unroll
    for (int mt = 0; mt < 4; mt++) {
        const int row = bm * 128 + wm * 64 + mt * 16 + (lane >> 2);
        const float inv0 = ginv[(size_t)bh * SS + row];
        const float inv1 = ginv[(size_t)bh * SS + row + 8];
        #pragma unroll
        for (int nt = 0; nt < 4; nt++) {
            const int col = wn * 32 + nt * 8 + (lane & 3) * 2;
            const float v0 = core.acc[mt][nt][0] * inv0;
            const float v1 = core.acc[mt][nt][1] * inv0;
            const float v2 = core.acc[mt][nt][2] * inv1;
            const float v3 = core.acc[mt][nt][3] * inv1;
            __nv_bfloat16 h0 = __float2bfloat16_rn(v0);
            __nv_bfloat16 h1 = __float2bfloat16_rn(v1);
            __nv_bfloat16 h2 = __float2bfloat16_rn(v2);
            __nv_bfloat16 h3 = __float2bfloat16_rn(v3);
            const size_t o0 = (size_t)(b * SS + row) * DD + h * DK + col;
            const size_t o1 = (size_t)(b * SS + row + 8) * DD + h * DK + col;
            *(uint32_t*)(xh + o0) = pack_bf2(h0, h1);
            *(uint32_t*)(xl + o0) = pack_bf2(
                __float2bfloat16_rn(v0 - __bfloat162float(h0)),
                __float2bfloat16_rn(v1 - __bfloat162float(h1)));
            *(uint32_t*)(xh + o1) = pack_bf2(h2, h3);
            *(uint32_t*)(xl + o1) = pack_bf2(
                __float2bfloat16_rn(v2 - __bfloat162float(h2)),
                __float2bfloat16_rn(v3 - __bfloat162float(h3)));
        }
    }
}

// ---------------------------------------------------------------------------
extern "C" void kernel_launch(void* const* d_in, const int* in_sizes, int n_in,
                              void* d_out, int out_size)
{
    const float* query = (const float*)d_in[0];
    const float* key   = (const float*)d_in[1];
    const float* value = (const float*)d_in[2];
    const float* Wq = (const float*)d_in[3];
    const float* bq = (const float*)d_in[4];
    const float* Wk = (const float*)d_in[5];
    const float* bk = (const float*)d_in[6];
    const float* Wv = (const float*)d_in[7];
    const float* bv = (const float*)d_in[8];
    const float* Wo = (const float*)d_in[9];
    const float* bo = (const float*)d_in[10];

    float* out  = (float*)d_out;                       // [4096, 2048]
    float* attn = out + (size_t)MTOK * DD;             // [32, 2048, 2048]

    float *v, *rpart, *ginv;
    __nv_bfloat16 *qih, *qil, *kih, *kil, *vih, *vil, *wh, *wl;
    __nv_bfloat16 *qh, *ql, *kh, *kl, *xh, *xl, *vth, *vtl, *eh, *el;
    cudaGetSymbolAddress((void**)&v, g_v);
    cudaGetSymbolAddress((void**)&rpart, g_rpart);
    cudaGetSymbolAddress((void**)&ginv, g_inv);
    cudaGetSymbolAddress((void**)&qih, g_qih);
    cudaGetSymbolAddress((void**)&qil, g_qil);
    cudaGetSymbolAddress((void**)&kih, g_kih);
    cudaGetSymbolAddress((void**)&kil, g_kil);
    cudaGetSymbolAddress((void**)&vih, g_vih);
    cudaGetSymbolAddress((void**)&vil, g_vil);
    cudaGetSymbolAddress((void**)&wh, g_wh);
    cudaGetSymbolAddress((void**)&wl, g_wl);
    cudaGetSymbolAddress((void**)&qh, g_qh);
    cudaGetSymbolAddress((void**)&ql, g_ql);
    cudaGetSymbolAddress((void**)&kh, g_kh);
    cudaGetSymbolAddress((void**)&kl, g_kl);
    cudaGetSymbolAddress((void**)&xh, g_xh);
    cudaGetSymbolAddress((void**)&xl, g_xl);
    cudaGetSymbolAddress((void**)&vth, g_vth);
    cudaGetSymbolAddress((void**)&vtl, g_vtl);
    cudaGetSymbolAddress((void**)&eh, g_eh);
    cudaGetSymbolAddress((void**)&el, g_el);

    static cudaStream_t s1 = nullptr;
    static cudaEvent_t evA = nullptr, evB = nullptr, evF = nullptr;
    if (s1 == nullptr) {
        cudaStreamCreateWithFlags(&s1, cudaStreamNonBlocking);
        cudaEventCreateWithFlags(&evA, cudaEventDisableTiming);
        cudaEventCreateWithFlags(&evB, cudaEventDisableTiming);
        cudaEventCreateWithFlags(&evF, cudaEventDisableTiming);
        cudaFuncSetAttribute(proj_qkv,
            cudaFuncAttributeMaxDynamicSharedMemorySize, DSMEM_TOTAL);
        cudaFuncSetAttribute(gemm_b16,
            cudaFuncAttributeMaxDynamicSharedMemorySize, DSMEM_TOTAL);
        cudaFuncSetAttribute(scores_exp_kernel,
            cudaFuncAttributeMaxDynamicSharedMemorySize, DSMEM_TOTAL);
        cudaFuncSetAttribute(av_mma_kernel,
            cudaFuncAttributeMaxDynamicSharedMemorySize, DSMEM_TOTAL);
    }

    // Fork side stream: zero the above-diagonal attn tail (no dependencies)
    cudaEventRecord(evA, 0);
    cudaStreamWaitEvent(s1, evA, 0);
    zero_tail<<<BB * HH * SS, 256, 0, s1>>>(attn);

    // Main stream: splits -> proj -> transpose -> scores -> ginv
    dim3 gsi((MTOK * DD) / (256 * 4), 3);
    split_inputs<<<gsi, 256>>>(query, key, value,
                               qih, qil, kih, kil, vih, vil);
    dim3 gsw((DD * DD) / (256 * 4), 4);
    split_weights<<<gsw, 256>>>(Wq, Wk, Wv, Wo, wh, wl);

    dim3 gproj(DD / 128, MTOK / 128, 3);
    proj_qkv<<<gproj, 256, DSMEM_TOTAL>>>(
        qih, qil, kih, kil, vih, vil, wh, wl, bq, bk, bv,
        qh, ql, kh, kl, v);

    dim3 gtr(SS / 32, DK / 32, BB * HH);
    transpose_v<<<gtr, 256>>>(v, vth, vtl);

    dim3 gsc(136, BB * HH);
    scores_exp_kernel<<<gsc, 256, DSMEM_TOTAL>>>(qh, ql, kh, kl, eh, el, rpart);

    ginv_kernel<<<(BB * HH * SS) / 256, 256>>>(rpart, ginv);

    // Side stream: finalize attn prefix (overlaps AV + output projection)
    cudaEventRecord(evB, 0);
    cudaStreamWaitEvent(s1, evB, 0);
    finalize_prefix<<<BB * HH * SS, 256, 0, s1>>>(eh, el, ginv, attn);
    cudaEventRecord(evF, s1);

    // Main stream: AV, output projection
    av_mma_kernel<<<512, 256, DSMEM_TOTAL>>>(eh, el, vth, vtl, ginv, xh, xl);

    dim3 gout(DD / 128, MTOK / 128);
    gemm_b16<<<gout, 256, DSMEM_TOTAL>>>(
        xh, xl, wh + (size_t)3 * DD * DD, wl + (size_t)3 * DD * DD, bo, out);

    // Join side stream into the graph
    cudaStreamWaitEvent(0, evF, 0);
}

// round 11
// speedup vs baseline: 1.2449x; 1.2449x over previous
#include <cuda_runtime.h>
#include <cuda_bf16.h>
#include <cstdint>
#include <math.h>

// ---------------------------------------------------------------------------
// Problem constants
// ---------------------------------------------------------------------------
#define BB   2
#define SS   2048
#define DD   2048
#define HH   16
#define DK   128
#define MTOK (BB * SS)          // 4096 tokens
#define SCALE 0.08838834764831845f  // 1/sqrt(128)

// Scratch (device globals; no cudaMalloc allowed)
static __device__ float g_v [(size_t)MTOK * DD];
static __device__ float g_rpart[(size_t)BB * HH * SS * 16];
static __device__ float g_inv[(size_t)BB * HH * SS];
// bf16 hi/lo planes
static __device__ __nv_bfloat16 g_qih[(size_t)MTOK * DD], g_qil[(size_t)MTOK * DD];
static __device__ __nv_bfloat16 g_kih[(size_t)MTOK * DD], g_kil[(size_t)MTOK * DD];
static __device__ __nv_bfloat16 g_vih[(size_t)MTOK * DD], g_vil[(size_t)MTOK * DD];
static __device__ __nv_bfloat16 g_wh[(size_t)4 * DD * DD], g_wl[(size_t)4 * DD * DD];
static __device__ __nv_bfloat16 g_qh[(size_t)MTOK * DD], g_ql[(size_t)MTOK * DD];
static __device__ __nv_bfloat16 g_kh[(size_t)MTOK * DD], g_kl[(size_t)MTOK * DD];
static __device__ __nv_bfloat16 g_xh[(size_t)MTOK * DD], g_xl[(size_t)MTOK * DD];
static __device__ __nv_bfloat16 g_vth[(size_t)BB * HH * DK * SS];
static __device__ __nv_bfloat16 g_vtl[(size_t)BB * HH * DK * SS];
// Unnormalized-E planes
static __device__ __nv_bfloat16 g_eh[(size_t)BB * HH * SS * SS];
static __device__ __nv_bfloat16 g_el[(size_t)BB * HH * SS * SS];

// ---------------------------------------------------------------------------
// PTX helpers
// ---------------------------------------------------------------------------
#define LDSM_X4(r0, r1, r2, r3, addr) \
    asm volatile("ldmatrix.sync.aligned.m8n8.x4.shared.b16 {%0,%1,%2,%3}, [%4];" \
        : "=r"(r0), "=r"(r1), "=r"(r2), "=r"(r3) : "r"(addr))

#define MMA16816(c, a0, a1, a2, a3, b0, b1) \
    asm volatile("mma.sync.aligned.m16n8k16.row.col.f32.bf16.bf16.f32 " \
        "{%0,%1,%2,%3}, {%4,%5,%6,%7}, {%8,%9}, {%0,%1,%2,%3};" \
        : "+f"((c)[0]), "+f"((c)[1]), "+f"((c)[2]), "+f"((c)[3]) \
        : "r"(a0), "r"(a1), "r"(a2), "r"(a3), "r"(b0), "r"(b1))

#define CP16(dst, src) \
    asm volatile("cp.async.cg.shared.global [%0], [%1], 16;" \
        :: "r"(dst), "l"(src))
#define CPCOMMIT() asm volatile("cp.async.commit_group;" ::: "memory")
#define CPWAIT2()  asm volatile("cp.async.wait_group 2;" ::: "memory")

__device__ __forceinline__ uint32_t smem_u32(const void* p) {
    uint32_t a;
    asm("{ .reg .u64 t; cvta.to.shared.u64 t, %1; cvt.u32.u64 %0, t; }"
        : "=r"(a) : "l"(p));
    return a;
}

__device__ __forceinline__ uint32_t pack_bf2(__nv_bfloat16 a, __nv_bfloat16 b) {
    return (uint32_t)__bfloat16_as_ushort(a) |
           ((uint32_t)__bfloat16_as_ushort(b) << 16);
}

__device__ __forceinline__ void split4(const float4 f, uint2& hi, uint2& lo) {
    __nv_bfloat16 h0 = __float2bfloat16_rn(f.x);
    __nv_bfloat16 h1 = __float2bfloat16_rn(f.y);
    __nv_bfloat16 h2 = __float2bfloat16_rn(f.z);
    __nv_bfloat16 h3 = __float2bfloat16_rn(f.w);
    __nv_bfloat16 l0 = __float2bfloat16_rn(f.x - __bfloat162float(h0));
    __nv_bfloat16 l1 = __float2bfloat16_rn(f.y - __bfloat162float(h1));
    __nv_bfloat16 l2 = __float2bfloat16_rn(f.z - __bfloat162float(h2));
    __nv_bfloat16 l3 = __float2bfloat16_rn(f.w - __bfloat162float(h3));
    hi.x = pack_bf2(h0, h1); hi.y = pack_bf2(h2, h3);
    lo.x = pack_bf2(l0, l1); lo.y = pack_bf2(l2, l3);
}

#define RS2 48

// ---------------------------------------------------------------------------
// MmaB16v2: 128x128 tile, K-chunk 16, 4-stage cp.async pipeline (2 CTAs/SM).
// Used by scores / AV (proven R8/R9 config).
// ---------------------------------------------------------------------------
#define NS 4
#define ST_AHI 0
#define ST_ALO 6144
#define ST_BHI 12288
#define ST_BLO 18432
#define ST_BYTES 24576
#define DSMEM_V2 (NS * ST_BYTES)   // 98304

struct MmaB16v2 {
    float acc[4][4][4];

    __device__ __forceinline__ static void issue(
        uint32_t sb,
        const __nv_bfloat16* Ah, const __nv_bfloat16* Al, size_t sA,
        const __nv_bfloat16* Bh, const __nv_bfloat16* Bl, size_t sB,
        int k0, int tid)
    {
        const int row  = tid >> 1;
        const int half = tid & 1;
        const uint32_t so = (uint32_t)row * RS2 + half * 16;
        const size_t oA = (size_t)row * sA + k0 + half * 8;
        const size_t oB = (size_t)row * sB + k0 + half * 8;
        CP16(sb + ST_AHI + so, Ah + oA);
        CP16(sb + ST_ALO + so, Al + oA);
        CP16(sb + ST_BHI + so, Bh + oB);
        CP16(sb + ST_BLO + so, Bl + oB);
    }

    __device__ __forceinline__ void run(
        uint32_t sbase,
        const __nv_bfloat16* Ah, const __nv_bfloat16* Al, size_t sA,
        const __nv_bfloat16* Bh, const __nv_bfloat16* Bl, size_t sB,
        const int nIter, const int tid)
    {
        const int lane = tid & 31;
        const int wid  = tid >> 5;
        const int wm   = wid >> 2;
        const int wn   = wid & 3;

        #pragma unroll
        for (int i = 0; i < 4; i++)
            #pragma unroll
            for (int j = 0; j < 4; j++)
                #pragma unroll
                for (int c = 0; c < 4; c++) acc[i][j][c] = 0.0f;

        const uint32_t aAddr = sbase + ST_AHI
            + (uint32_t)(wm * 64 + (lane & 15)) * RS2 + (lane >> 4) * 16;
        const uint32_t bAddr = sbase + ST_BHI
            + (uint32_t)(wn * 32 + (lane & 7) + ((lane >> 4) & 1) * 8) * RS2
            + ((lane >> 3) & 1) * 16;

        #pragma unroll
        for (int p = 0; p < NS - 1; p++) {
            if (p < nIter)
                issue(sbase + p * ST_BYTES, Ah, Al, sA, Bh, Bl, sB, p * 16, tid);
            CPCOMMIT();
        }

        for (int s = 0; s < nIter; s++) {
            CPWAIT2();
            __syncthreads();

            const uint32_t bo = (uint32_t)(s & (NS - 1)) * ST_BYTES;
            uint32_t ahi[4][4], alo[4][4];
            uint32_t bhi[2][4], blo[2][4];
            #pragma unroll
            for (int mt = 0; mt < 4; mt++) {
                const uint32_t a = aAddr + bo + mt * (16 * RS2);
                LDSM_X4(ahi[mt][0], ahi[mt][1], ahi[mt][2], ahi[mt][3], a);
                LDSM_X4(alo[mt][0], alo[mt][1], alo[mt][2], alo[mt][3],
                        a + (ST_ALO - ST_AHI));
            }
            #pragma unroll
            for (int pp = 0; pp < 2; pp++) {
                const uint32_t b = bAddr + bo + pp * (16 * RS2);
                LDSM_X4(bhi[pp][0], bhi[pp][1], bhi[pp][2], bhi[pp][3], b);
                LDSM_X4(blo[pp][0], blo[pp][1], blo[pp][2], blo[pp][3],
                        b + (ST_BLO - ST_BHI));
            }
            #pragma unroll
            for (int mt = 0; mt < 4; mt++) {
                #pragma unroll
                for (int pp = 0; pp < 2; pp++) {
                    #pragma unroll
                    for (int t = 0; t < 2; t++) {
                        const int nt = pp * 2 + t;
                        MMA16816(acc[mt][nt],
                                 ahi[mt][0], ahi[mt][1], ahi[mt][2], ahi[mt][3],
                                 bhi[pp][t * 2], bhi[pp][t * 2 + 1]);
                        MMA16816(acc[mt][nt],
                                 ahi[mt][0], ahi[mt][1], ahi[mt][2], ahi[mt][3],
                                 blo[pp][t * 2], blo[pp][t * 2 + 1]);
                        MMA16816(acc[mt][nt],
                                 alo[mt][0], alo[mt][1], alo[mt][2], alo[mt][3],
                                 bhi[pp][t * 2], bhi[pp][t * 2 + 1]);
                    }
                }
            }

            const int nx = s + NS - 1;
            if (nx < nIter)
                issue(sbase + (uint32_t)(nx & (NS - 1)) * ST_BYTES,
                      Ah, Al, sA, Bh, Bl, sB, nx * 16, tid);
            CPCOMMIT();
        }
        __syncthreads();
    }
};

// ---------------------------------------------------------------------------
// MmaB16v4: 128x64 tile, K-chunk 16, 4-stage pipeline, 3 CTAs/SM.
// Warp tile 32x32, acc=32 regs -> fits 84-reg budget without spilling.
// ---------------------------------------------------------------------------
#define W4_AHI 0
#define W4_ALO 6144
#define W4_BHI 12288
#define W4_BLO 15360
#define W4_BYTES 18432
#define DSMEM_V4 (NS * W4_BYTES)   // 73728

struct MmaB16v4 {
    float acc[2][4][4];

    __device__ __forceinline__ static void issue(
        uint32_t sb,
        const __nv_bfloat16* Ah, const __nv_bfloat16* Al, size_t sA,
        const __nv_bfloat16* Bh, const __nv_bfloat16* Bl, size_t sB,
        int k0, int tid)
    {
        // A: 128 rows x 2 halves = 256 cp16 per plane (1/thread/plane)
        const int arow = tid >> 1;
        const int ahalf = tid & 1;
        const uint32_t soA = (uint32_t)arow * RS2 + ahalf * 16;
        const size_t oA = (size_t)arow * sA + k0 + ahalf * 8;
        CP16(sb + W4_AHI + soA, Ah + oA);
        CP16(sb + W4_ALO + soA, Al + oA);
        // B: 64 rows x 2 halves x 2 planes = 256 cp16 (1/thread)
        const int brow = (tid & 127) >> 1;
        const int bhalf = tid & 1;
        const uint32_t soB = (uint32_t)brow * RS2 + bhalf * 16;
        const size_t oB = (size_t)brow * sB + k0 + bhalf * 8;
        if (tid < 128) CP16(sb + W4_BHI + soB, Bh + oB);
        else           CP16(sb + W4_BLO + soB, Bl + oB);
    }

    __device__ __forceinline__ void run(
        uint32_t sbase,
        const __nv_bfloat16* Ah, const __nv_bfloat16* Al, size_t sA,
        const __nv_bfloat16* Bh, const __nv_bfloat16* Bl, size_t sB,
        const int nIter, const int tid)
    {
        const int lane = tid & 31;
        const int wid  = tid >> 5;
        const int wm   = wid >> 1;          // 0..3 (32-row band)
        const int wn   = wid & 1;           // 0..1 (32-col band)

        #pragma unroll
        for (int i = 0; i < 2; i++)
            #pragma unroll
            for (int j = 0; j < 4; j++)
                #pragma unroll
                for (int c = 0; c < 4; c++) acc[i][j][c] = 0.0f;

        const uint32_t aAddr = sbase + W4_AHI
            + (uint32_t)(wm * 32 + (lane & 15)) * RS2 + (lane >> 4) * 16;
        const uint32_t bAddr = sbase + W4_BHI
            + (uint32_t)(wn * 32 + (lane & 7) + ((lane >> 4) & 1) * 8) * RS2
            + ((lane >> 3) & 1) * 16;

        #pragma unroll
        for (int p = 0; p < NS - 1; p++) {
            if (p < nIter)
                issue(sbase + p * W4_BYTES, Ah, Al, sA, Bh, Bl, sB, p * 16, tid);
            CPCOMMIT();
        }

        for (int s = 0; s < nIter; s++) {
            CPWAIT2();
            __syncthreads();

            const uint32_t bo = (uint32_t)(s & (NS - 1)) * W4_BYTES;
            uint32_t ahi[2][4], alo[2][4];
            uint32_t bhi[2][4], blo[2][4];
            #pragma unroll
            for (int mt = 0; mt < 2; mt++) {
                const uint32_t a = aAddr + bo + mt * (16 * RS2);
                LDSM_X4(ahi[mt][0], ahi[mt][1], ahi[mt][2], ahi[mt][3], a);
                LDSM_X4(alo[mt][0], alo[mt][1], alo[mt][2], alo[mt][3],
                        a + (W4_ALO - W4_AHI));
            }
            #pragma unroll
            for (int pp = 0; pp < 2; pp++) {
                const uint32_t b = bAddr + bo + pp * (16 * RS2);
                LDSM_X4(bhi[pp][0], bhi[pp][1], bhi[pp][2], bhi[pp][3], b);
                LDSM_X4(blo[pp][0], blo[pp][1], blo[pp][2], blo[pp][3],
                        b + (W4_BLO - W4_BHI));
            }
            #pragma unroll
            for (int mt = 0; mt < 2; mt++) {
                #pragma unroll
                for (int pp = 0; pp < 2; pp++) {
                    #pragma unroll
                    for (int t = 0; t < 2; t++) {
                        const int nt = pp * 2 + t;
                        MMA16816(acc[mt][nt],
                                 ahi[mt][0], ahi[mt][1], ahi[mt][2], ahi[mt][3],
                                 bhi[pp][t * 2], bhi[pp][t * 2 + 1]);
                        MMA16816(acc[mt][nt],
                                 ahi[mt][0], ahi[mt][1], ahi[mt][2], ahi[mt][3],
                                 blo[pp][t * 2], blo[pp][t * 2 + 1]);
                        MMA16816(acc[mt][nt],
                                 alo[mt][0], alo[mt][1], alo[mt][2], alo[mt][3],
                                 bhi[pp][t * 2], bhi[pp][t * 2 + 1]);
                    }
                }
            }

            const int nx = s + NS - 1;
            if (nx < nIter)
                issue(sbase + (uint32_t)(nx & (NS - 1)) * W4_BYTES,
                      Ah, Al, sA, Bh, Bl, sB, nx * 16, tid);
            CPCOMMIT();
        }
        __syncthreads();
    }
};

// ---------------------------------------------------------------------------
// Split fp32 tensors into bf16 hi/lo planes
// ---------------------------------------------------------------------------
__global__ __launch_bounds__(256) void split_inputs(
    const float* __restrict__ a0, const float* __restrict__ a1,
    const float* __restrict__ a2,
    __nv_bfloat16* __restrict__ h0, __nv_bfloat16* __restrict__ l0,
    __nv_bfloat16* __restrict__ h1, __nv_bfloat16* __restrict__ l1,
    __nv_bfloat16* __restrict__ h2, __nv_bfloat16* __restrict__ l2)
{
    const int z = blockIdx.y;
    const float* s = (z == 0) ? a0 : (z == 1) ? a1 : a2;
    __nv_bfloat16* H = (z == 0) ? h0 : (z == 1) ? h1 : h2;
    __nv_bfloat16* L = (z == 0) ? l0 : (z == 1) ? l1 : l2;
    const size_t i = ((size_t)blockIdx.x * 256 + threadIdx.x) * 4;
    float4 f = *(const float4*)(s + i);
    uint2 hi, lo;
    split4(f, hi, lo);
    *(uint2*)(H + i) = hi;
    *(uint2*)(L + i) = lo;
}

__global__ __launch_bounds__(256) void split_weights(
    const float* __restrict__ w0, const float* __restrict__ w1,
    const float* __restrict__ w2, const float* __restrict__ w3,
    __nv_bfloat16* __restrict__ wh, __nv_bfloat16* __restrict__ wl)
{
    const int z = blockIdx.y;
    const float* s = (z == 0) ? w0 : (z == 1) ? w1 : (z == 2) ? w2 : w3;
    const size_t base = (size_t)z * DD * DD;
    const size_t i = ((size_t)blockIdx.x * 256 + threadIdx.x) * 4;
    float4 f = *(const float4*)(s + i);
    uint2 hi, lo;
    split4(f, hi, lo);
    *(uint2*)(wh + base + i) = hi;
    *(uint2*)(wl + base + i) = lo;
}

// ---------------------------------------------------------------------------
// Batched Q/K/V projection (v4 core, tile 128x64): z=0 q, z=1 k, z=2 v(fp32)
// ---------------------------------------------------------------------------
__global__ __launch_bounds__(256, 3) void proj_qkv(
    const __nv_bfloat16* __restrict__ qih, const __nv_bfloat16* __restrict__ qil,
    const __nv_bfloat16* __restrict__ kih, const __nv_bfloat16* __restrict__ kil,
    const __nv_bfloat16* __restrict__ vih, const __nv_bfloat16* __restrict__ vil,
    const __nv_bfloat16* __restrict__ wh, const __nv_bfloat16* __restrict__ wl,
    const float* __restrict__ bq, const float* __restrict__ bk,
    const float* __restrict__ bv,
    __nv_bfloat16* __restrict__ qh, __nv_bfloat16* __restrict__ ql,
    __nv_bfloat16* __restrict__ kh, __nv_bfloat16* __restrict__ kl,
    float* __restrict__ v)
{
    extern __shared__ char dsm[];
    const uint32_t sbase = smem_u32(dsm);
    const int tid  = threadIdx.x;
    const int lane = tid & 31;
    const int wid  = tid >> 5;
    const int wm   = wid >> 1;
    const int wn   = wid & 1;
    const int bn   = blockIdx.x;       // 0..31 (64-col tiles)
    const int bm   = blockIdx.y;       // 0..31 (128-row tiles)
    const int z    = blockIdx.z;

    const __nv_bfloat16* Ah = (z == 0) ? qih : (z == 1) ? kih : vih;
    const __nv_bfloat16* Al = (z == 0) ? qil : (z == 1) ? kil : vil;
    const float* bias = (z == 0) ? bq : (z == 1) ? bk : bv;
    const size_t wbase = (size_t)z * DD * DD;

    MmaB16v4 core;
    core.run(sbase,
             Ah + (size_t)(bm * 128) * DD, Al + (size_t)(bm * 128) * DD, DD,
             wh + wbase + (size_t)(bn * 64) * DD,
             wl + wbase + (size_t)(bn * 64) * DD, DD,
             DD / 16, tid);

    #pragma unroll
    for (int mt = 0; mt < 2; mt++) {
        const int row = bm * 128 + wm * 32 + mt * 16 + (lane >> 2);
        #pragma unroll
        for (int nt = 0; nt < 4; nt++) {
            const int col = bn * 64 + wn * 32 + nt * 8 + (lane & 3) * 2;
            const float b0 = bias[col], b1 = bias[col + 1];
            const float v0 = core.acc[mt][nt][0] + b0;
            const float v1 = core.acc[mt][nt][1] + b1;
            const float v2 = core.acc[mt][nt][2] + b0;
            const float v3 = core.acc[mt][nt][3] + b1;
            if (z == 2) {
                *(float2*)(v + (size_t)row * DD + col) = make_float2(v0, v1);
                *(float2*)(v + (size_t)(row + 8) * DD + col) = make_float2(v2, v3);
            } else {
                __nv_bfloat16* H = (z == 0) ? qh : kh;
                __nv_bfloat16* L = (z == 0) ? ql : kl;
                __nv_bfloat16 h0 = __float2bfloat16_rn(v0);
                __nv_bfloat16 h1 = __float2bfloat16_rn(v1);
                __nv_bfloat16 h2 = __float2bfloat16_rn(v2);
                __nv_bfloat16 h3 = __float2bfloat16_rn(v3);
                *(uint32_t*)(H + (size_t)row * DD + col) = pack_bf2(h0, h1);
                *(uint32_t*)(L + (size_t)row * DD + col) = pack_bf2(
                    __float2bfloat16_rn(v0 - __bfloat162float(h0)),
                    __float2bfloat16_rn(v1 - __bfloat162float(h1)));
                *(uint32_t*)(H + (size_t)(row + 8) * DD + col) = pack_bf2(h2, h3);
                *(uint32_t*)(L + (size_t)(row + 8) * DD + col) = pack_bf2(
                    __float2bfloat16_rn(v2 - __bfloat162float(h2)),
                    __float2bfloat16_rn(v3 - __bfloat162float(h3)));
            }
        }
    }
}

// ---------------------------------------------------------------------------
// Final GEMM (v4 core, tile 128x64): out = x @ Wo^T + bo
// ---------------------------------------------------------------------------
__global__ __launch_bounds__(256, 3) void gemm_b16(
    const __nv_bfloat16* __restrict__ Ah, const __nv_bfloat16* __restrict__ Al,
    const __nv_bfloat16* __restrict__ Wh, const __nv_bfloat16* __restrict__ Wl,
    const float* __restrict__ bias, float* __restrict__ C)
{
    extern __shared__ char dsm[];
    const uint32_t sbase = smem_u32(dsm);
    const int tid  = threadIdx.x;
    const int lane = tid & 31;
    const int wid  = tid >> 5;
    const int wm   = wid >> 1;
    const int wn   = wid & 1;
    const int bn   = blockIdx.x;
    const int bm   = blockIdx.y;

    MmaB16v4 core;
    core.run(sbase,
             Ah + (size_t)(bm * 128) * DD, Al + (size_t)(bm * 128) * DD, DD,
             Wh + (size_t)(bn * 64) * DD, Wl + (size_t)(bn * 64) * DD, DD,
             DD / 16, tid);

    #pragma unroll
    for (int mt = 0; mt < 2; mt++) {
        const int row = bm * 128 + wm * 32 + mt * 16 + (lane >> 2);
        #pragma unroll
        for (int nt = 0; nt < 4; nt++) {
            const int col = bn * 64 + wn * 32 + nt * 8 + (lane & 3) * 2;
            const float b0 = bias[col], b1 = bias[col + 1];
            float2 o0, o1;
            o0.x = core.acc[mt][nt][0] + b0; o0.y = core.acc[mt][nt][1] + b1;
            o1.x = core.acc[mt][nt][2] + b0; o1.y = core.acc[mt][nt][3] + b1;
            *(float2*)(C + (size_t)row * DD + col) = o0;
            *(float2*)(C + (size_t)(row + 8) * DD + col) = o1;
        }
    }
}

// ---------------------------------------------------------------------------
// Scores+exp (v2 core): triangular grid; E planes + row-sum partials.
// ---------------------------------------------------------------------------
__global__ __launch_bounds__(256) void scores_exp_kernel(
    const __nv_bfloat16* __restrict__ qh, const __nv_bfloat16* __restrict__ ql,
    const __nv_bfloat16* __restrict__ kh, const __nv_bfloat16* __restrict__ kl,
    __nv_bfloat16* __restrict__ eh, __nv_bfloat16* __restrict__ el,
    float* __restrict__ rpart)
{
    const int idx = blockIdx.x;            // 0..135 (lower-triangle tile id)
    int bm = (int)((sqrtf(8.f * idx + 1.f) - 1.f) * 0.5f);
    while ((bm + 1) * (bm + 2) / 2 <= idx) bm++;
    while (bm * (bm + 1) / 2 > idx) bm--;
    const int bn = idx - bm * (bm + 1) / 2;
    const int bh = blockIdx.y;
    const int tid = threadIdx.x;

    extern __shared__ char dsm[];
    __shared__ float rs[128][4];
    const uint32_t sbase = smem_u32(dsm);
    const int lane = tid & 31;
    const int wid  = tid >> 5;
    const int wm   = wid >> 2;
    const int wn   = wid & 3;
    const int b = bh / HH, h = bh % HH;

    const size_t aoff = (size_t)(b * SS + bm * 128) * DD + h * DK;
    const size_t boff = (size_t)(b * SS + bn * 128) * DD + h * DK;

    MmaB16v2 core;
    core.run(sbase, qh + aoff, ql + aoff, DD, kh + boff, kl + boff, DD,
             DK / 16, tid);

    __nv_bfloat16* peh = eh + (size_t)bh * SS * SS;
    __nv_bfloat16* pel = el + (size_t)bh * SS * SS;

    float rsum[4][2];
    #pragma unroll
    for (int mt = 0; mt < 4; mt++) { rsum[mt][0] = 0.f; rsum[mt][1] = 0.f; }

    #pragma unroll
    for (int mt = 0; mt < 4; mt++) {
        const int r0 = bm * 128 + wm * 64 + mt * 16 + (lane >> 2);
        const int r1 = r0 + 8;
        #pragma unroll
        for (int nt = 0; nt < 4; nt++) {
            const int col = bn * 128 + wn * 32 + nt * 8 + (lane & 3) * 2;
            float e0 = (col     <= r0) ? __expf(core.acc[mt][nt][0] * SCALE) : 0.f;
            float e1 = (col + 1 <= r0) ? __expf(core.acc[mt][nt][1] * SCALE) : 0.f;
            float e2 = (col     <= r1) ? __expf(core.acc[mt][nt][2] * SCALE) : 0.f;
            float e3 = (col + 1 <= r1) ? __expf(core.acc[mt][nt][3] * SCALE) : 0.f;
            rsum[mt][0] += e0 + e1;
            rsum[mt][1] += e2 + e3;
            __nv_bfloat16 h0 = __float2bfloat16_rn(e0);
            __nv_bfloat16 h1 = __float2bfloat16_rn(e1);
            __nv_bfloat16 h2 = __float2bfloat16_rn(e2);
            __nv_bfloat16 h3 = __float2bfloat16_rn(e3);
            *(uint32_t*)(peh + (size_t)r0 * SS + col) = pack_bf2(h0, h1);
            *(uint32_t*)(pel + (size_t)r0 * SS + col) = pack_bf2(
                __float2bfloat16_rn(e0 - __bfloat162float(h0)),
                __float2bfloat16_rn(e1 - __bfloat162float(h1)));
            *(uint32_t*)(peh + (size_t)r1 * SS + col) = pack_bf2(h2, h3);
            *(uint32_t*)(pel + (size_t)r1 * SS + col) = pack_bf2(
                __float2bfloat16_rn(e2 - __bfloat162float(h2)),
                __float2bfloat16_rn(e3 - __bfloat162float(h3)));
        }
    }

    #pragma unroll
    for (int mt = 0; mt < 4; mt++) {
        #pragma unroll
        for (int hf = 0; hf < 2; hf++) {
            float vv = rsum[mt][hf];
            vv += __shfl_xor_sync(0xffffffffu, vv, 1);
            vv += __shfl_xor_sync(0xffffffffu, vv, 2);
            if ((lane & 3) == 0) {
                const int lrow = wm * 64 + mt * 16 + hf * 8 + (lane >> 2);
                rs[lrow][wn] = vv;
            }
        }
    }
    __syncthreads();
    if (tid < 128) {
        const float p = rs[tid][0] + rs[tid][1] + rs[tid][2] + rs[tid][3];
        rpart[((size_t)bh * SS + bm * 128 + tid) * 16 + bn] = p;
    }
}

// ---------------------------------------------------------------------------
// ginv: 1/rowsum from partials
// ---------------------------------------------------------------------------
__global__ __launch_bounds__(256) void ginv_kernel(
    const float* __restrict__ rpart, float* __restrict__ ginv)
{
    const int i = blockIdx.x * 256 + threadIdx.x;   // bh*SS + s
    const int s = i & (SS - 1);
    const float* p = rpart + (size_t)i * 16;
    const int nb = (s >> 7) + 1;
    float sum = 0.f;
    for (int k = 0; k < nb; k++) sum += p[k];
    ginv[i] = 1.0f / sum;
}

// ---------------------------------------------------------------------------
// Zero the above-diagonal tail of attn (side stream)
// ---------------------------------------------------------------------------
__global__ __launch_bounds__(256) void zero_tail(float* __restrict__ attn)
{
    const int blk = blockIdx.x;           // bh*SS + s
    const int s   = blk & (SS - 1);
    const int limit = ((s >> 7) + 1) * 128;
    float* row = attn + (size_t)blk * SS;
    const float4 z = make_float4(0.f, 0.f, 0.f, 0.f);
    for (int j = limit + threadIdx.x * 4; j < SS; j += 1024)
        *(float4*)(row + j) = z;
}

// ---------------------------------------------------------------------------
// Finalize (prefix only): attn[0..limit) = (Eh+El)*inv. Tail pre-zeroed.
// ---------------------------------------------------------------------------
__global__ __launch_bounds__(256) void finalize_prefix(
    const __nv_bfloat16* __restrict__ eh, const __nv_bfloat16* __restrict__ el,
    const float* __restrict__ ginv, float* __restrict__ attn)
{
    const int blk = blockIdx.x;           // bh*SS + s
    const int s   = blk & (SS - 1);
    const float inv = ginv[blk];
    const __nv_bfloat16* reh = eh + (size_t)blk * SS;
    const __nv_bfloat16* rel = el + (size_t)blk * SS;
    float* row = attn + (size_t)blk * SS;
    const int limit = ((s >> 7) + 1) * 128;
    for (int j = threadIdx.x * 4; j < limit; j += 1024) {
        const __nv_bfloat162 h2 = *(const __nv_bfloat162*)(reh + j);
        const __nv_bfloat162 h3 = *(const __nv_bfloat162*)(reh + j + 2);
        const __nv_bfloat162 l2 = *(const __nv_bfloat162*)(rel + j);
        const __nv_bfloat162 l3 = *(const __nv_bfloat162*)(rel + j + 2);
        float4 o;
        o.x = (__bfloat162float(h2.x) + __bfloat162float(l2.x)) * inv;
        o.y = (__bfloat162float(h2.y) + __bfloat162float(l2.y)) * inv;
        o.z = (__bfloat162float(h3.x) + __bfloat162float(l3.x)) * inv;
        o.w = (__bfloat162float(h3.y) + __bfloat162float(l3.y)) * inv;
        *(float4*)(row + j) = o;
    }
}

// ---------------------------------------------------------------------------
// Transpose V per head into bf16 hi/lo planes: vt[bh][d][s]
// ---------------------------------------------------------------------------
__global__ __launch_bounds__(256) void transpose_v(
    const float* __restrict__ v,
    __nv_bfloat16* __restrict__ vth, __nv_bfloat16* __restrict__ vtl)
{
    __shared__ float t[32][33];
    const int bh = blockIdx.z, b = bh / HH, h = bh % HH;
    const int s0 = blockIdx.x * 32, d0 = blockIdx.y * 32;
    const int tx = threadIdx.x & 31, ty = threadIdx.x >> 5;
    #pragma unroll
    for (int i = 0; i < 4; i++)
        t[ty + i * 8][tx] =
            v[(size_t)(b * SS + s0 + ty + i * 8) * DD + h * DK + d0 + tx];
    __syncthreads();
    #pragma unroll
    for (int i = 0; i < 4; i++) {
        const float f = t[tx][ty + i * 8];
        const __nv_bfloat16 hh = __float2bfloat16_rn(f);
        const __nv_bfloat16 ll = __float2bfloat16_rn(f - __bfloat162float(hh));
        const size_t idx = (size_t)bh * DK * SS + (size_t)(d0 + ty + i * 8) * SS
                         + s0 + tx;
        vth[idx] = hh;
        vtl[idx] = ll;
    }
}

// ---------------------------------------------------------------------------
// AV (v2 core): x = (E @ V) * inv; heavy-first 1D grid.
// ---------------------------------------------------------------------------
__global__ __launch_bounds__(256) void av_mma_kernel(
    const __nv_bfloat16* __restrict__ eh, const __nv_bfloat16* __restrict__ el,
    const __nv_bfloat16* __restrict__ vth, const __nv_bfloat16* __restrict__ vtl,
    const float* __restrict__ ginv,
    __nv_bfloat16* __restrict__ xh, __nv_bfloat16* __restrict__ xl)
{
    const int t = blockIdx.x;              // 0..511, heavy bm first
    const int bm = 15 - (t >> 5);
    const int bh = t & 31;
    extern __shared__ char dsm[];
    const uint32_t sbase = smem_u32(dsm);
    const int b = bh / HH, h = bh % HH;
    const int tid  = threadIdx.x;
    const int lane = tid & 31;
    const int wid  = tid >> 5;
    const int wm   = wid >> 2;
    const int wn   = wid & 3;

    const size_t aoff = (size_t)bh * SS * SS + (size_t)(bm * 128) * SS;
    const size_t boff = (size_t)bh * DK * SS;

    MmaB16v2 core;
    core.run(sbase, eh + aoff, el + aoff, SS, vth + boff, vtl + boff, SS,
             (bm + 1) * 8, tid);

    #pragma unroll
    for (int mt = 0; mt < 4; mt++) {
        const int row = bm * 128 + wm * 64 + mt * 16 + (lane >> 2);
        const float inv0 = ginv[(size_t)bh * SS + row];
        const float inv1 = ginv[(size_t)bh * SS + row + 8];
        #pragma unroll
        for (int nt = 0; nt < 4; nt++) {
            const int col = wn * 32 + nt * 8 + (lane & 3) * 2;
            const float v0 = core.acc[mt][nt][0] * inv0;
            const float v1 = core.acc[mt][nt][1] * inv0;
            const float v2 = core.acc[mt][nt][2] * inv1;
            const float v3 = core.acc[mt][nt][3] * inv1;
            __nv_bfloat16 h0 = __float2bfloat16_rn(v0);
            __nv_bfloat16 h1 = __float2bfloat16_rn(v1);
            __nv_bfloat16 h2 = __float2bfloat16_rn(v2);
            __nv_bfloat16 h3 = __float2bfloat16_rn(v3);
            const size_t o0 = (size_t)(b * SS + row) * DD + h * DK + col;
            const size_t o1 = (size_t)(b * SS + row + 8) * DD + h * DK + col;
            *(uint32_t*)(xh + o0) = pack_bf2(h0, h1);
            *(uint32_t*)(xl + o0) = pack_bf2(
                __float2bfloat16_rn(v0 - __bfloat162float(h0)),
                __float2bfloat16_rn(v1 - __bfloat162float(h1)));
            *(uint32_t*)(xh + o1) = pack_bf2(h2, h3);
            *(uint32_t*)(xl + o1) = pack_bf2(
                __float2bfloat16_rn(v2 - __bfloat162float(h2)),
                __float2bfloat16_rn(v3 - __bfloat162float(h3)));
        }
    }
}

// ---------------------------------------------------------------------------
extern "C" void kernel_launch(void* const* d_in, const int* in_sizes, int n_in,
                              void* d_out, int out_size)
{
    const float* query = (const float*)d_in[0];
    const float* key   = (const float*)d_in[1];
    const float* value = (const float*)d_in[2];
    const float* Wq = (const float*)d_in[3];
    const float* bq = (const float*)d_in[4];
    const float* Wk = (const float*)d_in[5];
    const float* bk = (const float*)d_in[6];
    const float* Wv = (const float*)d_in[7];
    const float* bv = (const float*)d_in[8];
    const float* Wo = (const float*)d_in[9];
    const float* bo = (const float*)d_in[10];

    float* out  = (float*)d_out;                       // [4096, 2048]
    float* attn = out + (size_t)MTOK * DD;             // [32, 2048, 2048]

    float *v, *rpart, *ginv;
    __nv_bfloat16 *qih, *qil, *kih, *kil, *vih, *vil, *wh, *wl;
    __nv_bfloat16 *qh, *ql, *kh, *kl, *xh, *xl, *vth, *vtl, *eh, *el;
    cudaGetSymbolAddress((void**)&v, g_v);
    cudaGetSymbolAddress((void**)&rpart, g_rpart);
    cudaGetSymbolAddress((void**)&ginv, g_inv);
    cudaGetSymbolAddress((void**)&qih, g_qih);
    cudaGetSymbolAddress((void**)&qil, g_qil);
    cudaGetSymbolAddress((void**)&kih, g_kih);
    cudaGetSymbolAddress((void**)&kil, g_kil);
    cudaGetSymbolAddress((void**)&vih, g_vih);
    cudaGetSymbolAddress((void**)&vil, g_vil);
    cudaGetSymbolAddress((void**)&wh, g_wh);
    cudaGetSymbolAddress((void**)&wl, g_wl);
    cudaGetSymbolAddress((void**)&qh, g_qh);
    cudaGetSymbolAddress((void**)&ql, g_ql);
    cudaGetSymbolAddress((void**)&kh, g_kh);
    cudaGetSymbolAddress((void**)&kl, g_kl);
    cudaGetSymbolAddress((void**)&xh, g_xh);
    cudaGetSymbolAddress((void**)&xl, g_xl);
    cudaGetSymbolAddress((void**)&vth, g_vth);
    cudaGetSymbolAddress((void**)&vtl, g_vtl);
    cudaGetSymbolAddress((void**)&eh, g_eh);
    cudaGetSymbolAddress((void**)&el, g_el);

    static cudaStream_t s1 = nullptr;
    static cudaEvent_t evA = nullptr, evB = nullptr, evF = nullptr;
    if (s1 == nullptr) {
        cudaStreamCreateWithFlags(&s1, cudaStreamNonBlocking);
        cudaEventCreateWithFlags(&evA, cudaEventDisableTiming);
        cudaEventCreateWithFlags(&evB, cudaEventDisableTiming);
        cudaEventCreateWithFlags(&evF, cudaEventDisableTiming);
        cudaFuncSetAttribute(proj_qkv,
            cudaFuncAttributeMaxDynamicSharedMemorySize, DSMEM_V4);
        cudaFuncSetAttribute(gemm_b16,
            cudaFuncAttributeMaxDynamicSharedMemorySize, DSMEM_V4);
        cudaFuncSetAttribute(scores_exp_kernel,
            cudaFuncAttributeMaxDynamicSharedMemorySize, DSMEM_V2);
        cudaFuncSetAttribute(av_mma_kernel,
            cudaFuncAttributeMaxDynamicSharedMemorySize, DSMEM_V2);
    }

    // Fork side stream: zero the above-diagonal attn tail (no dependencies)
    cudaEventRecord(evA, 0);
    cudaStreamWaitEvent(s1, evA, 0);
    zero_tail<<<BB * HH * SS, 256, 0, s1>>>(attn);

    // Main stream: splits -> proj -> transpose -> scores -> ginv
    dim3 gsi((MTOK * DD) / (256 * 4), 3);
    split_inputs<<<gsi, 256>>>(query, key, value,
                               qih, qil, kih, kil, vih, vil);
    dim3 gsw((DD * DD) / (256 * 4), 4);
    split_weights<<<gsw, 256>>>(Wq, Wk, Wv, Wo, wh, wl);

    dim3 gproj(DD / 64, MTOK / 128, 3);                 // (32, 32, 3)
    proj_qkv<<<gproj, 256, DSMEM_V4>>>(
        qih, qil, kih, kil, vih, vil, wh, wl, bq, bk, bv,
        qh, ql, kh, kl, v);

    dim3 gtr(SS / 32, DK / 32, BB * HH);
    transpose_v<<<gtr, 256>>>(v, vth, vtl);

    dim3 gsc(136, BB * HH);
    scores_exp_kernel<<<gsc, 256, DSMEM_V2>>>(qh, ql, kh, kl, eh, el, rpart);

    ginv_kernel<<<(BB * HH * SS) / 256, 256>>>(rpart, ginv);

    // Side stream: finalize attn prefix (overlaps AV + output projection)
    cudaEventRecord(evB, 0);
    cudaStreamWaitEvent(s1, evB, 0);
    finalize_prefix<<<BB * HH * SS, 256, 0, s1>>>(eh, el, ginv, attn);
    cudaEventRecord(evF, s1);

    // Main stream: AV, output projection
    av_mma_kernel<<<512, 256, DSMEM_V2>>>(eh, el, vth, vtl, ginv, xh, xl);

    dim3 gout(DD / 64, MTOK / 128);                     // (32, 32)
    gemm_b16<<<gout, 256, DSMEM_V4>>>(
        xh, xl, wh + (size_t)3 * DD * DD, wl + (size_t)3 * DD * DD, bo, out);

    // Join side stream into the graph
    cudaStreamWaitEvent(0, evF, 0);
}

// round 12
// speedup vs baseline: 1.8731x; 1.5047x over previous
#include <cuda_runtime.h>
#include <cuda_bf16.h>
#include <cstdint>
#include <math.h>

// ---------------------------------------------------------------------------
// Problem constants
// ---------------------------------------------------------------------------
#define BB   2
#define SS   2048
#define DD   2048
#define HH   16
#define DK   128
#define MTOK (BB * SS)          // 4096 tokens
#define SCALE 0.08838834764831845f  // 1/sqrt(128)

// Scratch (device globals; no cudaMalloc allowed)
static __device__ float g_v [(size_t)MTOK * DD];
static __device__ float g_rpart[(size_t)BB * HH * SS * 16];
static __device__ float g_inv[(size_t)BB * HH * SS];
// bf16 hi/lo planes
static __device__ __nv_bfloat16 g_qih[(size_t)MTOK * DD], g_qil[(size_t)MTOK * DD];
static __device__ __nv_bfloat16 g_kih[(size_t)MTOK * DD], g_kil[(size_t)MTOK * DD];
static __device__ __nv_bfloat16 g_vih[(size_t)MTOK * DD], g_vil[(size_t)MTOK * DD];
static __device__ __nv_bfloat16 g_wh[(size_t)4 * DD * DD], g_wl[(size_t)4 * DD * DD];
static __device__ __nv_bfloat16 g_qh[(size_t)MTOK * DD], g_ql[(size_t)MTOK * DD];
static __device__ __nv_bfloat16 g_kh[(size_t)MTOK * DD], g_kl[(size_t)MTOK * DD];
static __device__ __nv_bfloat16 g_xh[(size_t)MTOK * DD], g_xl[(size_t)MTOK * DD];
static __device__ __nv_bfloat16 g_vth[(size_t)BB * HH * DK * SS];
static __device__ __nv_bfloat16 g_vtl[(size_t)BB * HH * DK * SS];
// Unnormalized-E planes
static __device__ __nv_bfloat16 g_eh[(size_t)BB * HH * SS * SS];
static __device__ __nv_bfloat16 g_el[(size_t)BB * HH * SS * SS];

// ---------------------------------------------------------------------------
// PTX helpers
// ---------------------------------------------------------------------------
#define LDSM_X4(r0, r1, r2, r3, addr) \
    asm volatile("ldmatrix.sync.aligned.m8n8.x4.shared.b16 {%0,%1,%2,%3}, [%4];" \
        : "=r"(r0), "=r"(r1), "=r"(r2), "=r"(r3) : "r"(addr))

#define MMA16816(c, a0, a1, a2, a3, b0, b1) \
    asm volatile("mma.sync.aligned.m16n8k16.row.col.f32.bf16.bf16.f32 " \
        "{%0,%1,%2,%3}, {%4,%5,%6,%7}, {%8,%9}, {%0,%1,%2,%3};" \
        : "+f"((c)[0]), "+f"((c)[1]), "+f"((c)[2]), "+f"((c)[3]) \
        : "r"(a0), "r"(a1), "r"(a2), "r"(a3), "r"(b0), "r"(b1))

#define CP16(dst, src) \
    asm volatile("cp.async.cg.shared.global [%0], [%1], 16;" \
        :: "r"(dst), "l"(src))
#define CPCOMMIT() asm volatile("cp.async.commit_group;" ::: "memory")
#define CPWAIT2()  asm volatile("cp.async.wait_group 2;" ::: "memory")

__device__ __forceinline__ uint32_t smem_u32(const void* p) {
    uint32_t a;
    asm("{ .reg .u64 t; cvta.to.shared.u64 t, %1; cvt.u32.u64 %0, t; }"
        : "=r"(a) : "l"(p));
    return a;
}

__device__ __forceinline__ uint32_t pack_bf2(__nv_bfloat16 a, __nv_bfloat16 b) {
    return (uint32_t)__bfloat16_as_ushort(a) |
           ((uint32_t)__bfloat16_as_ushort(b) << 16);
}

__device__ __forceinline__ void split4(const float4 f, uint2& hi, uint2& lo) {
    __nv_bfloat16 h0 = __float2bfloat16_rn(f.x);
    __nv_bfloat16 h1 = __float2bfloat16_rn(f.y);
    __nv_bfloat16 h2 = __float2bfloat16_rn(f.z);
    __nv_bfloat16 h3 = __float2bfloat16_rn(f.w);
    __nv_bfloat16 l0 = __float2bfloat16_rn(f.x - __bfloat162float(h0));
    __nv_bfloat16 l1 = __float2bfloat16_rn(f.y - __bfloat162float(h1));
    __nv_bfloat16 l2 = __float2bfloat16_rn(f.z - __bfloat162float(h2));
    __nv_bfloat16 l3 = __float2bfloat16_rn(f.w - __bfloat162float(h3));
    hi.x = pack_bf2(h0, h1); hi.y = pack_bf2(h2, h3);
    lo.x = pack_bf2(l0, l1); lo.y = pack_bf2(l2, l3);
}

#define RS2 48
#define NS 4

// ---------------------------------------------------------------------------
// MmaB16v2: 128x128 tile, 256 thr, K-chunk 16, 4-stage pipeline (2 CTAs/SM).
// Used by scores / AV (proven R9 config — natural regs, no spills).
// ---------------------------------------------------------------------------
#define ST_AHI 0
#define ST_ALO 6144
#define ST_BHI 12288
#define ST_BLO 18432
#define ST_BYTES 24576
#define DSMEM_V2 (NS * ST_BYTES)   // 98304

struct MmaB16v2 {
    float acc[4][4][4];

    __device__ __forceinline__ static void issue(
        uint32_t sb,
        const __nv_bfloat16* Ah, const __nv_bfloat16* Al, size_t sA,
        const __nv_bfloat16* Bh, const __nv_bfloat16* Bl, size_t sB,
        int k0, int tid)
    {
        const int row  = tid >> 1;
        const int half = tid & 1;
        const uint32_t so = (uint32_t)row * RS2 + half * 16;
        const size_t oA = (size_t)row * sA + k0 + half * 8;
        const size_t oB = (size_t)row * sB + k0 + half * 8;
        CP16(sb + ST_AHI + so, Ah + oA);
        CP16(sb + ST_ALO + so, Al + oA);
        CP16(sb + ST_BHI + so, Bh + oB);
        CP16(sb + ST_BLO + so, Bl + oB);
    }

    __device__ __forceinline__ void run(
        uint32_t sbase,
        const __nv_bfloat16* Ah, const __nv_bfloat16* Al, size_t sA,
        const __nv_bfloat16* Bh, const __nv_bfloat16* Bl, size_t sB,
        const int nIter, const int tid)
    {
        const int lane = tid & 31;
        const int wid  = tid >> 5;
        const int wm   = wid >> 2;
        const int wn   = wid & 3;

        #pragma unroll
        for (int i = 0; i < 4; i++)
            #pragma unroll
            for (int j = 0; j < 4; j++)
                #pragma unroll
                for (int c = 0; c < 4; c++) acc[i][j][c] = 0.0f;

        const uint32_t aAddr = sbase + ST_AHI
            + (uint32_t)(wm * 64 + (lane & 15)) * RS2 + (lane >> 4) * 16;
        const uint32_t bAddr = sbase + ST_BHI
            + (uint32_t)(wn * 32 + (lane & 7) + ((lane >> 4) & 1) * 8) * RS2
            + ((lane >> 3) & 1) * 16;

        #pragma unroll
        for (int p = 0; p < NS - 1; p++) {
            if (p < nIter)
                issue(sbase + p * ST_BYTES, Ah, Al, sA, Bh, Bl, sB, p * 16, tid);
            CPCOMMIT();
        }

        for (int s = 0; s < nIter; s++) {
            CPWAIT2();
            __syncthreads();

            const uint32_t bo = (uint32_t)(s & (NS - 1)) * ST_BYTES;
            uint32_t ahi[4][4], alo[4][4];
            uint32_t bhi[2][4], blo[2][4];
            #pragma unroll
            for (int mt = 0; mt < 4; mt++) {
                const uint32_t a = aAddr + bo + mt * (16 * RS2);
                LDSM_X4(ahi[mt][0], ahi[mt][1], ahi[mt][2], ahi[mt][3], a);
                LDSM_X4(alo[mt][0], alo[mt][1], alo[mt][2], alo[mt][3],
                        a + (ST_ALO - ST_AHI));
            }
            #pragma unroll
            for (int pp = 0; pp < 2; pp++) {
                const uint32_t b = bAddr + bo + pp * (16 * RS2);
                LDSM_X4(bhi[pp][0], bhi[pp][1], bhi[pp][2], bhi[pp][3], b);
                LDSM_X4(blo[pp][0], blo[pp][1], blo[pp][2], blo[pp][3],
                        b + (ST_BLO - ST_BHI));
            }
            #pragma unroll
            for (int mt = 0; mt < 4; mt++) {
                #pragma unroll
                for (int pp = 0; pp < 2; pp++) {
                    #pragma unroll
                    for (int t = 0; t < 2; t++) {
                        const int nt = pp * 2 + t;
                        MMA16816(acc[mt][nt],
                                 ahi[mt][0], ahi[mt][1], ahi[mt][2], ahi[mt][3],
                                 bhi[pp][t * 2], bhi[pp][t * 2 + 1]);
                        MMA16816(acc[mt][nt],
                                 ahi[mt][0], ahi[mt][1], ahi[mt][2], ahi[mt][3],
                                 blo[pp][t * 2], blo[pp][t * 2 + 1]);
                        MMA16816(acc[mt][nt],
                                 alo[mt][0], alo[mt][1], alo[mt][2], alo[mt][3],
                                 bhi[pp][t * 2], bhi[pp][t * 2 + 1]);
                    }
                }
            }

            const int nx = s + NS - 1;
            if (nx < nIter)
                issue(sbase + (uint32_t)(nx & (NS - 1)) * ST_BYTES,
                      Ah, Al, sA, Bh, Bl, sB, nx * 16, tid);
            CPCOMMIT();
        }
        __syncthreads();
    }
};

// ---------------------------------------------------------------------------
// MmaB16v5: 256x128 tile, 512 threads, K-chunk 16, 4-stage pipeline.
// 16 warps, warp tile 64x32 (acc=64 regs, natural allocation, NO reg cap).
// 25% fewer cp.async ops per MMA than v2; 1 CTA/SM (regs), 144KB smem.
// ---------------------------------------------------------------------------
#define W5_AHI 0
#define W5_ALO 12288
#define W5_BHI 24576
#define W5_BLO 30720
#define W5_BYTES 36864
#define DSMEM_V5 (NS * W5_BYTES)   // 147456

struct MmaB16v5 {
    float acc[4][4][4];

    __device__ __forceinline__ static void issue(
        uint32_t sb,
        const __nv_bfloat16* Ah, const __nv_bfloat16* Al, size_t sA,
        const __nv_bfloat16* Bh, const __nv_bfloat16* Bl, size_t sB,
        int k0, int tid)
    {
        // A: 256 rows x 2 halves x 2 planes = 1024 cp16 (2 per thread)
        const int arow = tid >> 1;              // 0..255
        const int ahalf = tid & 1;
        const uint32_t soA = (uint32_t)arow * RS2 + ahalf * 16;
        const size_t oA = (size_t)arow * sA + k0 + ahalf * 8;
        CP16(sb + W5_AHI + soA, Ah + oA);
        CP16(sb + W5_ALO + soA, Al + oA);
        // B: 128 rows x 2 halves x 2 planes = 512 cp16 (1 per thread)
        const int brow = (tid & 255) >> 1;      // 0..127
        const int bhalf = tid & 1;
        const uint32_t soB = (uint32_t)brow * RS2 + bhalf * 16;
        const size_t oB = (size_t)brow * sB + k0 + bhalf * 8;
        if (tid < 256) CP16(sb + W5_BHI + soB, Bh + oB);
        else           CP16(sb + W5_BLO + soB, Bl + oB);
    }

    __device__ __forceinline__ void run(
        uint32_t sbase,
        const __nv_bfloat16* Ah, const __nv_bfloat16* Al, size_t sA,
        const __nv_bfloat16* Bh, const __nv_bfloat16* Bl, size_t sB,
        const int nIter, const int tid)
    {
        const int lane = tid & 31;
        const int wid  = tid >> 5;          // 0..15
        const int wm   = wid >> 2;          // 0..3 (64-row band of 256)
        const int wn   = wid & 3;           // 0..3 (32-col band of 128)

        #pragma unroll
        for (int i = 0; i < 4; i++)
            #pragma unroll
            for (int j = 0; j < 4; j++)
                #pragma unroll
                for (int c = 0; c < 4; c++) acc[i][j][c] = 0.0f;

        const uint32_t aAddr = sbase + W5_AHI
            + (uint32_t)(wm * 64 + (lane & 15)) * RS2 + (lane >> 4) * 16;
        const uint32_t bAddr = sbase + W5_BHI
            + (uint32_t)(wn * 32 + (lane & 7) + ((lane >> 4) & 1) * 8) * RS2
            + ((lane >> 3) & 1) * 16;

        #pragma unroll
        for (int p = 0; p < NS - 1; p++) {
            if (p < nIter)
                issue(sbase + p * W5_BYTES, Ah, Al, sA, Bh, Bl, sB, p * 16, tid);
            CPCOMMIT();
        }

        for (int s = 0; s < nIter; s++) {
            CPWAIT2();
            __syncthreads();

            const uint32_t bo = (uint32_t)(s & (NS - 1)) * W5_BYTES;
            uint32_t ahi[4][4], alo[4][4];
            uint32_t bhi[2][4], blo[2][4];
            #pragma unroll
            for (int mt = 0; mt < 4; mt++) {
                const uint32_t a = aAddr + bo + mt * (16 * RS2);
                LDSM_X4(ahi[mt][0], ahi[mt][1], ahi[mt][2], ahi[mt][3], a);
                LDSM_X4(alo[mt][0], alo[mt][1], alo[mt][2], alo[mt][3],
                        a + (W5_ALO - W5_AHI));
            }
            #pragma unroll
            for (int pp = 0; pp < 2; pp++) {
                const uint32_t b = bAddr + bo + pp * (16 * RS2);
                LDSM_X4(bhi[pp][0], bhi[pp][1], bhi[pp][2], bhi[pp][3], b);
                LDSM_X4(blo[pp][0], blo[pp][1], blo[pp][2], blo[pp][3],
                        b + (W5_BLO - W5_BHI));
            }
            #pragma unroll
            for (int mt = 0; mt < 4; mt++) {
                #pragma unroll
                for (int pp = 0; pp < 2; pp++) {
                    #pragma unroll
                    for (int t = 0; t < 2; t++) {
                        const int nt = pp * 2 + t;
                        MMA16816(acc[mt][nt],
                                 ahi[mt][0], ahi[mt][1], ahi[mt][2], ahi[mt][3],
                                 bhi[pp][t * 2], bhi[pp][t * 2 + 1]);
                        MMA16816(acc[mt][nt],
                                 ahi[mt][0], ahi[mt][1], ahi[mt][2], ahi[mt][3],
                                 blo[pp][t * 2], blo[pp][t * 2 + 1]);
                        MMA16816(acc[mt][nt],
                                 alo[mt][0], alo[mt][1], alo[mt][2], alo[mt][3],
                                 bhi[pp][t * 2], bhi[pp][t * 2 + 1]);
                    }
                }
            }

            const int nx = s + NS - 1;
            if (nx < nIter)
                issue(sbase + (uint32_t)(nx & (NS - 1)) * W5_BYTES,
                      Ah, Al, sA, Bh, Bl, sB, nx * 16, tid);
            CPCOMMIT();
        }
        __syncthreads();
    }
};

// ---------------------------------------------------------------------------
// Split fp32 tensors into bf16 hi/lo planes
// ---------------------------------------------------------------------------
__global__ __launch_bounds__(256) void split_inputs(
    const float* __restrict__ a0, const float* __restrict__ a1,
    const float* __restrict__ a2,
    __nv_bfloat16* __restrict__ h0, __nv_bfloat16* __restrict__ l0,
    __nv_bfloat16* __restrict__ h1, __nv_bfloat16* __restrict__ l1,
    __nv_bfloat16* __restrict__ h2, __nv_bfloat16* __restrict__ l2)
{
    const int z = blockIdx.y;
    const float* s = (z == 0) ? a0 : (z == 1) ? a1 : a2;
    __nv_bfloat16* H = (z == 0) ? h0 : (z == 1) ? h1 : h2;
    __nv_bfloat16* L = (z == 0) ? l0 : (z == 1) ? l1 : l2;
    const size_t i = ((size_t)blockIdx.x * 256 + threadIdx.x) * 4;
    float4 f = *(const float4*)(s + i);
    uint2 hi, lo;
    split4(f, hi, lo);
    *(uint2*)(H + i) = hi;
    *(uint2*)(L + i) = lo;
}

__global__ __launch_bounds__(256) void split_weights(
    const float* __restrict__ w0, const float* __restrict__ w1,
    const float* __restrict__ w2, const float* __restrict__ w3,
    __nv_bfloat16* __restrict__ wh, __nv_bfloat16* __restrict__ wl)
{
    const int z = blockIdx.y;
    const float* s = (z == 0) ? w0 : (z == 1) ? w1 : (z == 2) ? w2 : w3;
    const size_t base = (size_t)z * DD * DD;
    const size_t i = ((size_t)blockIdx.x * 256 + threadIdx.x) * 4;
    float4 f = *(const float4*)(s + i);
    uint2 hi, lo;
    split4(f, hi, lo);
    *(uint2*)(wh + base + i) = hi;
    *(uint2*)(wl + base + i) = lo;
}

// ---------------------------------------------------------------------------
// Batched Q/K/V projection (v5 core, tile 256x128, 512 threads)
// ---------------------------------------------------------------------------
__global__ __launch_bounds__(512) void proj_qkv(
    const __nv_bfloat16* __restrict__ qih, const __nv_bfloat16* __restrict__ qil,
    const __nv_bfloat16* __restrict__ kih, const __nv_bfloat16* __restrict__ kil,
    const __nv_bfloat16* __restrict__ vih, const __nv_bfloat16* __restrict__ vil,
    const __nv_bfloat16* __restrict__ wh, const __nv_bfloat16* __restrict__ wl,
    const float* __restrict__ bq, const float* __restrict__ bk,
    const float* __restrict__ bv,
    __nv_bfloat16* __restrict__ qh, __nv_bfloat16* __restrict__ ql,
    __nv_bfloat16* __restrict__ kh, __nv_bfloat16* __restrict__ kl,
    float* __restrict__ v)
{
    extern __shared__ char dsm[];
    const uint32_t sbase = smem_u32(dsm);
    const int tid  = threadIdx.x;
    const int lane = tid & 31;
    const int wid  = tid >> 5;
    const int wm   = wid >> 2;
    const int wn   = wid & 3;
    const int bn   = blockIdx.x;        // 0..15 (128-col tiles)
    const int bm   = blockIdx.y;        // 0..15 (256-row tiles)
    const int z    = blockIdx.z;

    const __nv_bfloat16* Ah = (z == 0) ? qih : (z == 1) ? kih : vih;
    const __nv_bfloat16* Al = (z == 0) ? qil : (z == 1) ? kil : vil;
    const float* bias = (z == 0) ? bq : (z == 1) ? bk : bv;
    const size_t wbase = (size_t)z * DD * DD;

    MmaB16v5 core;
    core.run(sbase,
             Ah + (size_t)(bm * 256) * DD, Al + (size_t)(bm * 256) * DD, DD,
             wh + wbase + (size_t)(bn * 128) * DD,
             wl + wbase + (size_t)(bn * 128) * DD, DD,
             DD / 16, tid);

    #pragma unroll
    for (int mt = 0; mt < 4; mt++) {
        const int row = bm * 256 + wm * 64 + mt * 16 + (lane >> 2);
        #pragma unroll
        for (int nt = 0; nt < 4; nt++) {
            const int col = bn * 128 + wn * 32 + nt * 8 + (lane & 3) * 2;
            const float b0 = bias[col], b1 = bias[col + 1];
            const float v0 = core.acc[mt][nt][0] + b0;
            const float v1 = core.acc[mt][nt][1] + b1;
            const float v2 = core.acc[mt][nt][2] + b0;
            const float v3 = core.acc[mt][nt][3] + b1;
            if (z == 2) {
                *(float2*)(v + (size_t)row * DD + col) = make_float2(v0, v1);
                *(float2*)(v + (size_t)(row + 8) * DD + col) = make_float2(v2, v3);
            } else {
                __nv_bfloat16* H = (z == 0) ? qh : kh;
                __nv_bfloat16* L = (z == 0) ? ql : kl;
                __nv_bfloat16 h0 = __float2bfloat16_rn(v0);
                __nv_bfloat16 h1 = __float2bfloat16_rn(v1);
                __nv_bfloat16 h2 = __float2bfloat16_rn(v2);
                __nv_bfloat16 h3 = __float2bfloat16_rn(v3);
                *(uint32_t*)(H + (size_t)row * DD + col) = pack_bf2(h0, h1);
                *(uint32_t*)(L + (size_t)row * DD + col) = pack_bf2(
                    __float2bfloat16_rn(v0 - __bfloat162float(h0)),
                    __float2bfloat16_rn(v1 - __bfloat162float(h1)));
                *(uint32_t*)(H + (size_t)(row + 8) * DD + col) = pack_bf2(h2, h3);
                *(uint32_t*)(L + (size_t)(row + 8) * DD + col) = pack_bf2(
                    __float2bfloat16_rn(v2 - __bfloat162float(h2)),
                    __float2bfloat16_rn(v3 - __bfloat162float(h3)));
            }
        }
    }
}

// ---------------------------------------------------------------------------
// Final GEMM (v5 core, tile 256x128, 512 threads): out = x @ Wo^T + bo
// ---------------------------------------------------------------------------
__global__ __launch_bounds__(512) void gemm_b16(
    const __nv_bfloat16* __restrict__ Ah, const __nv_bfloat16* __restrict__ Al,
    const __nv_bfloat16* __restrict__ Wh, const __nv_bfloat16* __restrict__ Wl,
    const float* __restrict__ bias, float* __restrict__ C)
{
    extern __shared__ char dsm[];
    const uint32_t sbase = smem_u32(dsm);
    const int tid  = threadIdx.x;
    const int lane = tid & 31;
    const int wid  = tid >> 5;
    const int wm   = wid >> 2;
    const int wn   = wid & 3;
    const int bn   = blockIdx.x;
    const int bm   = blockIdx.y;

    MmaB16v5 core;
    core.run(sbase,
             Ah + (size_t)(bm * 256) * DD, Al + (size_t)(bm * 256) * DD, DD,
             Wh + (size_t)(bn * 128) * DD, Wl + (size_t)(bn * 128) * DD, DD,
             DD / 16, tid);

    #pragma unroll
    for (int mt = 0; mt < 4; mt++) {
        const int row = bm * 256 + wm * 64 + mt * 16 + (lane >> 2);
        #pragma unroll
        for (int nt = 0; nt < 4; nt++) {
            const int col = bn * 128 + wn * 32 + nt * 8 + (lane & 3) * 2;
            const float b0 = bias[col], b1 = bias[col + 1];
            float2 o0, o1;
            o0.x = core.acc[mt][nt][0] + b0; o0.y = core.acc[mt][nt][1] + b1;
            o1.x = core.acc[mt][nt][2] + b0; o1.y = core.acc[mt][nt][3] + b1;
            *(float2*)(C + (size_t)row * DD + col) = o0;
            *(float2*)(C + (size_t)(row + 8) * DD + col) = o1;
        }
    }
}

// ---------------------------------------------------------------------------
// Scores+exp (v2 core): triangular grid; E planes + row-sum partials.
// ---------------------------------------------------------------------------
__global__ __launch_bounds__(256) void scores_exp_kernel(
    const __nv_bfloat16* __restrict__ qh, const __nv_bfloat16* __restrict__ ql,
    const __nv_bfloat16* __restrict__ kh, const __nv_bfloat16* __restrict__ kl,
    __nv_bfloat16* __restrict__ eh, __nv_bfloat16* __restrict__ el,
    float* __restrict__ rpart)
{
    const int idx = blockIdx.x;            // 0..135 (lower-triangle tile id)
    int bm = (int)((sqrtf(8.f * idx + 1.f) - 1.f) * 0.5f);
    while ((bm + 1) * (bm + 2) / 2 <= idx) bm++;
    while (bm * (bm + 1) / 2 > idx) bm--;
    const int bn = idx - bm * (bm + 1) / 2;
    const int bh = blockIdx.y;
    const int tid = threadIdx.x;

    extern __shared__ char dsm[];
    __shared__ float rs[128][4];
    const uint32_t sbase = smem_u32(dsm);
    const int lane = tid & 31;
    const int wid  = tid >> 5;
    const int wm   = wid >> 2;
    const int wn   = wid & 3;
    const int b = bh / HH, h = bh % HH;

    const size_t aoff = (size_t)(b * SS + bm * 128) * DD + h * DK;
    const size_t boff = (size_t)(b * SS + bn * 128) * DD + h * DK;

    MmaB16v2 core;
    core.run(sbase, qh + aoff, ql + aoff, DD, kh + boff, kl + boff, DD,
             DK / 16, tid);

    __nv_bfloat16* peh = eh + (size_t)bh * SS * SS;
    __nv_bfloat16* pel = el + (size_t)bh * SS * SS;

    float rsum[4][2];
    #pragma unroll
    for (int mt = 0; mt < 4; mt++) { rsum[mt][0] = 0.f; rsum[mt][1] = 0.f; }

    #pragma unroll
    for (int mt = 0; mt < 4; mt++) {
        const int r0 = bm * 128 + wm * 64 + mt * 16 + (lane >> 2);
        const int r1 = r0 + 8;
        #pragma unroll
        for (int nt = 0; nt < 4; nt++) {
            const int col = bn * 128 + wn * 32 + nt * 8 + (lane & 3) * 2;
            float e0 = (col     <= r0) ? __expf(core.acc[mt][nt][0] * SCALE) : 0.f;
            float e1 = (col + 1 <= r0) ? __expf(core.acc[mt][nt][1] * SCALE) : 0.f;
            float e2 = (col     <= r1) ? __expf(core.acc[mt][nt][2] * SCALE) : 0.f;
            float e3 = (col + 1 <= r1) ? __expf(core.acc[mt][nt][3] * SCALE) : 0.f;
            rsum[mt][0] += e0 + e1;
            rsum[mt][1] += e2 + e3;
            __nv_bfloat16 h0 = __float2bfloat16_rn(e0);
            __nv_bfloat16 h1 = __float2bfloat16_rn(e1);
            __nv_bfloat16 h2 = __float2bfloat16_rn(e2);
            __nv_bfloat16 h3 = __float2bfloat16_rn(e3);
            *(uint32_t*)(peh + (size_t)r0 * SS + col) = pack_bf2(h0, h1);
            *(uint32_t*)(pel + (size_t)r0 * SS + col) = pack_bf2(
                __float2bfloat16_rn(e0 - __bfloat162float(h0)),
                __float2bfloat16_rn(e1 - __bfloat162float(h1)));
            *(uint32_t*)(peh + (size_t)r1 * SS + col) = pack_bf2(h2, h3);
            *(uint32_t*)(pel + (size_t)r1 * SS + col) = pack_bf2(
                __float2bfloat16_rn(e2 - __bfloat162float(h2)),
                __float2bfloat16_rn(e3 - __bfloat162float(h3)));
        }
    }

    #pragma unroll
    for (int mt = 0; mt < 4; mt++) {
        #pragma unroll
        for (int hf = 0; hf < 2; hf++) {
            float vv = rsum[mt][hf];
            vv += __shfl_xor_sync(0xffffffffu, vv, 1);
            vv += __shfl_xor_sync(0xffffffffu, vv, 2);
            if ((lane & 3) == 0) {
                const int lrow = wm * 64 + mt * 16 + hf * 8 + (lane >> 2);
                rs[lrow][wn] = vv;
            }
        }
    }
    __syncthreads();
    if (tid < 128) {
        const float p = rs[tid][0] + rs[tid][1] + rs[tid][2] + rs[tid][3];
        rpart[((size_t)bh * SS + bm * 128 + tid) * 16 + bn] = p;
    }
}

// ---------------------------------------------------------------------------
// ginv: 1/rowsum from partials
// ---------------------------------------------------------------------------
__global__ __launch_bounds__(256) void ginv_kernel(
    const float* __restrict__ rpart, float* __restrict__ ginv)
{
    const int i = blockIdx.x * 256 + threadIdx.x;   // bh*SS + s
    const int s = i & (SS - 1);
    const float* p = rpart + (size_t)i * 16;
    const int nb = (s >> 7) + 1;
    float sum = 0.f;
    for (int k = 0; k < nb; k++) sum += p[k];
    ginv[i] = 1.0f / sum;
}

// ---------------------------------------------------------------------------
// Zero the above-diagonal tail of attn (side stream)
// ---------------------------------------------------------------------------
__global__ __launch_bounds__(256) void zero_tail(float* __restrict__ attn)
{
    const int blk = blockIdx.x;           // bh*SS + s
    const int s   = blk & (SS - 1);
    const int limit = ((s >> 7) + 1) * 128;
    float* row = attn + (size_t)blk * SS;
    const float4 z = make_float4(0.f, 0.f, 0.f, 0.f);
    for (int j = limit + threadIdx.x * 4; j < SS; j += 1024)
        *(float4*)(row + j) = z;
}

// ---------------------------------------------------------------------------
// Finalize (prefix only): attn[0..limit) = (Eh+El)*inv. Tail pre-zeroed.
// ---------------------------------------------------------------------------
__global__ __launch_bounds__(256) void finalize_prefix(
    const __nv_bfloat16* __restrict__ eh, const __nv_bfloat16* __restrict__ el,
    const float* __restrict__ ginv, float* __restrict__ attn)
{
    const int blk = blockIdx.x;           // bh*SS + s
    const int s   = blk & (SS - 1);
    const float inv = ginv[blk];
    const __nv_bfloat16* reh = eh + (size_t)blk * SS;
    const __nv_bfloat16* rel = el + (size_t)blk * SS;
    float* row = attn + (size_t)blk * SS;
    const int limit = ((s >> 7) + 1) * 128;
    for (int j = threadIdx.x * 4; j < limit; j += 1024) {
        const __nv_bfloat162 h2 = *(const __nv_bfloat162*)(reh + j);
        const __nv_bfloat162 h3 = *(const __nv_bfloat162*)(reh + j + 2);
        const __nv_bfloat162 l2 = *(const __nv_bfloat162*)(rel + j);
        const __nv_bfloat162 l3 = *(const __nv_bfloat162*)(rel + j + 2);
        float4 o;
        o.x = (__bfloat162float(h2.x) + __bfloat162float(l2.x)) * inv;
        o.y = (__bfloat162float(h2.y) + __bfloat162float(l2.y)) * inv;
        o.z = (__bfloat162float(h3.x) + __bfloat162float(l3.x)) * inv;
        o.w = (__bfloat162float(h3.y) + __bfloat162float(l3.y)) * inv;
        *(float4*)(row + j) = o;
    }
}

// ---------------------------------------------------------------------------
// Transpose V per head into bf16 hi/lo planes: vt[bh][d][s]
// ---------------------------------------------------------------------------
__global__ __launch_bounds__(256) void transpose_v(
    const float* __restrict__ v,
    __nv_bfloat16* __restrict__ vth, __nv_bfloat16* __restrict__ vtl)
{
    __shared__ float t[32][33];
    const int bh = blockIdx.z, b = bh / HH, h = bh % HH;
    const int s0 = blockIdx.x * 32, d0 = blockIdx.y * 32;
    const int tx = threadIdx.x & 31, ty = threadIdx.x >> 5;
    #pragma unroll
    for (int i = 0; i < 4; i++)
        t[ty + i * 8][tx] =
            v[(size_t)(b * SS + s0 + ty + i * 8) * DD + h * DK + d0 + tx];
    __syncthreads();
    #pragma unroll
    for (int i = 0; i < 4; i++) {
        const float f = t[tx][ty + i * 8];
        const __nv_bfloat16 hh = __float2bfloat16_rn(f);
        const __nv_bfloat16 ll = __float2bfloat16_rn(f - __bfloat162float(hh));
        const size_t idx = (size_t)bh * DK * SS + (size_t)(d0 + ty + i * 8) * SS
                         + s0 + tx;
        vth[idx] = hh;
        vtl[idx] = ll;
    }
}

// ---------------------------------------------------------------------------
// AV (v2 core): x = (E @ V) * inv; heavy-first 1D grid.
// ---------------------------------------------------------------------------
__global__ __launch_bounds__(256) void av_mma_kernel(
    const __nv_bfloat16* __restrict__ eh, const __nv_bfloat16* __restrict__ el,
    const __nv_bfloat16* __restrict__ vth, const __nv_bfloat16* __restrict__ vtl,
    const float* __restrict__ ginv,
    __nv_bfloat16* __restrict__ xh, __nv_bfloat16* __restrict__ xl)
{
    const int t = blockIdx.x;              // 0..511, heavy bm first
    const int bm = 15 - (t >> 5);
    const int bh = t & 31;
    extern __shared__ char dsm[];
    const uint32_t sbase = smem_u32(dsm);
    const int b = bh / HH, h = bh % HH;
    const int tid  = threadIdx.x;
    const int lane = tid & 31;
    const int wid  = tid >> 5;
    const int wm   = wid >> 2;
    const int wn   = wid & 3;

    const size_t aoff = (size_t)bh * SS * SS + (size_t)(bm * 128) * SS;
    const size_t boff = (size_t)bh * DK * SS;

    MmaB16v2 core;
    core.run(sbase, eh + aoff, el + aoff, SS, vth + boff, vtl + boff, SS,
             (bm + 1) * 8, tid);

    #pragma unroll
    for (int mt = 0; mt < 4; mt++) {
        const int row = bm * 128 + wm * 64 + mt * 16 + (lane >> 2);
        const float inv0 = ginv[(size_t)bh * SS + row];
        const float inv1 = ginv[(size_t)bh * SS + row + 8];
        #pragma unroll
        for (int nt = 0; nt < 4; nt++) {
            const int col = wn * 32 + nt * 8 + (lane & 3) * 2;
            const float v0 = core.acc[mt][nt][0] * inv0;
            const float v1 = core.acc[mt][nt][1] * inv0;
            const float v2 = core.acc[mt][nt][2] * inv1;
            const float v3 = core.acc[mt][nt][3] * inv1;
            __nv_bfloat16 h0 = __float2bfloat16_rn(v0);
            __nv_bfloat16 h1 = __float2bfloat16_rn(v1);
            __nv_bfloat16 h2 = __float2bfloat16_rn(v2);
            __nv_bfloat16 h3 = __float2bfloat16_rn(v3);
            const size_t o0 = (size_t)(b * SS + row) * DD + h * DK + col;
            const size_t o1 = (size_t)(b * SS + row + 8) * DD + h * DK + col;
            *(uint32_t*)(xh + o0) = pack_bf2(h0, h1);
            *(uint32_t*)(xl + o0) = pack_bf2(
                __float2bfloat16_rn(v0 - __bfloat162float(h0)),
                __float2bfloat16_rn(v1 - __bfloat162float(h1)));
            *(uint32_t*)(xh + o1) = pack_bf2(h2, h3);
            *(uint32_t*)(xl + o1) = pack_bf2(
                __float2bfloat16_rn(v2 - __bfloat162float(h2)),
                __float2bfloat16_rn(v3 - __bfloat162float(h3)));
        }
    }
}

// ---------------------------------------------------------------------------
extern "C" void kernel_launch(void* const* d_in, const int* in_sizes, int n_in,
                              void* d_out, int out_size)
{
    const float* query = (const float*)d_in[0];
    const float* key   = (const float*)d_in[1];
    const float* value = (const float*)d_in[2];
    const float* Wq = (const float*)d_in[3];
    const float* bq = (const float*)d_in[4];
    const float* Wk = (const float*)d_in[5];
    const float* bk = (const float*)d_in[6];
    const float* Wv = (const float*)d_in[7];
    const float* bv = (const float*)d_in[8];
    const float* Wo = (const float*)d_in[9];
    const float* bo = (const float*)d_in[10];

    float* out  = (float*)d_out;                       // [4096, 2048]
    float* attn = out + (size_t)MTOK * DD;             // [32, 2048, 2048]

    float *v, *rpart, *ginv;
    __nv_bfloat16 *qih, *qil, *kih, *kil, *vih, *vil, *wh, *wl;
    __nv_bfloat16 *qh, *ql, *kh, *kl, *xh, *xl, *vth, *vtl, *eh, *el;
    cudaGetSymbolAddress((void**)&v, g_v);
    cudaGetSymbolAddress((void**)&rpart, g_rpart);
    cudaGetSymbolAddress((void**)&ginv, g_inv);
    cudaGetSymbolAddress((void**)&qih, g_qih);
    cudaGetSymbolAddress((void**)&qil, g_qil);
    cudaGetSymbolAddress((void**)&kih, g_kih);
    cudaGetSymbolAddress((void**)&kil, g_kil);
    cudaGetSymbolAddress((void**)&vih, g_vih);
    cudaGetSymbolAddress((void**)&vil, g_vil);
    cudaGetSymbolAddress((void**)&wh, g_wh);
    cudaGetSymbolAddress((void**)&wl, g_wl);
    cudaGetSymbolAddress((void**)&qh, g_qh);
    cudaGetSymbolAddress((void**)&ql, g_ql);
    cudaGetSymbolAddress((void**)&kh, g_kh);
    cudaGetSymbolAddress((void**)&kl, g_kl);
    cudaGetSymbolAddress((void**)&xh, g_xh);
    cudaGetSymbolAddress((void**)&xl, g_xl);
    cudaGetSymbolAddress((void**)&vth, g_vth);
    cudaGetSymbolAddress((void**)&vtl, g_vtl);
    cudaGetSymbolAddress((void**)&eh, g_eh);
    cudaGetSymbolAddress((void**)&el, g_el);

    static cudaStream_t s1 = nullptr;
    static cudaEvent_t evA = nullptr, evB = nullptr, evF = nullptr;
    if (s1 == nullptr) {
        cudaStreamCreateWithFlags(&s1, cudaStreamNonBlocking);
        cudaEventCreateWithFlags(&evA, cudaEventDisableTiming);
        cudaEventCreateWithFlags(&evB, cudaEventDisableTiming);
        cudaEventCreateWithFlags(&evF, cudaEventDisableTiming);
        cudaFuncSetAttribute(proj_qkv,
            cudaFuncAttributeMaxDynamicSharedMemorySize, DSMEM_V5);
        cudaFuncSetAttribute(gemm_b16,
            cudaFuncAttributeMaxDynamicSharedMemorySize, DSMEM_V5);
        cudaFuncSetAttribute(scores_exp_kernel,
            cudaFuncAttributeMaxDynamicSharedMemorySize, DSMEM_V2);
        cudaFuncSetAttribute(av_mma_kernel,
            cudaFuncAttributeMaxDynamicSharedMemorySize, DSMEM_V2);
    }

    // Fork side stream: zero the above-diagonal attn tail (no dependencies)
    cudaEventRecord(evA, 0);
    cudaStreamWaitEvent(s1, evA, 0);
    zero_tail<<<BB * HH * SS, 256, 0, s1>>>(attn);

    // Main stream: splits -> proj -> transpose -> scores -> ginv
    dim3 gsi((MTOK * DD) / (256 * 4), 3);
    split_inputs<<<gsi, 256>>>(query, key, value,
                               qih, qil, kih, kil, vih, vil);
    dim3 gsw((DD * DD) / (256 * 4), 4);
    split_weights<<<gsw, 256>>>(Wq, Wk, Wv, Wo, wh, wl);

    dim3 gproj(DD / 128, MTOK / 256, 3);                // (16, 16, 3)
    proj_qkv<<<gproj, 512, DSMEM_V5>>>(
        qih, qil, kih, kil, vih, vil, wh, wl, bq, bk, bv,
        qh, ql, kh, kl, v);

    dim3 gtr(SS / 32, DK / 32, BB * HH);
    transpose_v<<<gtr, 256>>>(v, vth, vtl);

    dim3 gsc(136, BB * HH);
    scores_exp_kernel<<<gsc, 256, DSMEM_V2>>>(qh, ql, kh, kl, eh, el, rpart);

    ginv_kernel<<<(BB * HH * SS) / 256, 256>>>(rpart, ginv);

    // Side stream: finalize attn prefix (overlaps AV + output projection)
    cudaEventRecord(evB, 0);
    cudaStreamWaitEvent(s1, evB, 0);
    finalize_prefix<<<BB * HH * SS, 256, 0, s1>>>(eh, el, ginv, attn);
    cudaEventRecord(evF, s1);

    // Main stream: AV, output projection
    av_mma_kernel<<<512, 256, DSMEM_V2>>>(eh, el, vth, vtl, ginv, xh, xl);

    dim3 gout(DD / 128, MTOK / 256);                    // (16, 16)
    gemm_b16<<<gout, 512, DSMEM_V5>>>(
        xh, xl, wh + (size_t)3 * DD * DD, wl + (size_t)3 * DD * DD, bo, out);

    // Join side stream into the graph
    cudaStreamWaitEvent(0, evF, 0);
}

// round 13
// speedup vs baseline: 2.1689x; 1.1579x over previous
#include <cuda_runtime.h>
#include <cuda_bf16.h>
#include <cstdint>
#include <math.h>

// ---------------------------------------------------------------------------
// Problem constants
// ---------------------------------------------------------------------------
#define BB   2
#define SS   2048
#define DD   2048
#define HH   16
#define DK   128
#define MTOK (BB * SS)          // 4096 tokens
#define SCALE 0.08838834764831845f  // 1/sqrt(128)

// Scratch (device globals; no cudaMalloc allowed)
static __device__ float g_v [(size_t)MTOK * DD];
static __device__ float g_rpart[(size_t)BB * HH * SS * 16];
static __device__ float g_inv[(size_t)BB * HH * SS];
// bf16 hi/lo planes
static __device__ __nv_bfloat16 g_qih[(size_t)MTOK * DD], g_qil[(size_t)MTOK * DD];
static __device__ __nv_bfloat16 g_kih[(size_t)MTOK * DD], g_kil[(size_t)MTOK * DD];
static __device__ __nv_bfloat16 g_vih[(size_t)MTOK * DD], g_vil[(size_t)MTOK * DD];
static __device__ __nv_bfloat16 g_wh[(size_t)4 * DD * DD], g_wl[(size_t)4 * DD * DD];
static __device__ __nv_bfloat16 g_qh[(size_t)MTOK * DD], g_ql[(size_t)MTOK * DD];
static __device__ __nv_bfloat16 g_kh[(size_t)MTOK * DD], g_kl[(size_t)MTOK * DD];
static __device__ __nv_bfloat16 g_xh[(size_t)MTOK * DD], g_xl[(size_t)MTOK * DD];
static __device__ __nv_bfloat16 g_vth[(size_t)BB * HH * DK * SS];
static __device__ __nv_bfloat16 g_vtl[(size_t)BB * HH * DK * SS];
// Unnormalized-E planes
static __device__ __nv_bfloat16 g_eh[(size_t)BB * HH * SS * SS];
static __device__ __nv_bfloat16 g_el[(size_t)BB * HH * SS * SS];

// ---------------------------------------------------------------------------
// PTX helpers
// ---------------------------------------------------------------------------
#define LDSM_X4(r0, r1, r2, r3, addr) \
    asm volatile("ldmatrix.sync.aligned.m8n8.x4.shared.b16 {%0,%1,%2,%3}, [%4];" \
        : "=r"(r0), "=r"(r1), "=r"(r2), "=r"(r3) : "r"(addr))

#define MMA16816(c, a0, a1, a2, a3, b0, b1) \
    asm volatile("mma.sync.aligned.m16n8k16.row.col.f32.bf16.bf16.f32 " \
        "{%0,%1,%2,%3}, {%4,%5,%6,%7}, {%8,%9}, {%0,%1,%2,%3};" \
        : "+f"((c)[0]), "+f"((c)[1]), "+f"((c)[2]), "+f"((c)[3]) \
        : "r"(a0), "r"(a1), "r"(a2), "r"(a3), "r"(b0), "r"(b1))

#define CP16(dst, src) \
    asm volatile("cp.async.cg.shared.global [%0], [%1], 16;" \
        :: "r"(dst), "l"(src))
#define CPCOMMIT() asm volatile("cp.async.commit_group;" ::: "memory")
#define CPWAIT2()  asm volatile("cp.async.wait_group 2;" ::: "memory")

__device__ __forceinline__ uint32_t smem_u32(const void* p) {
    uint32_t a;
    asm("{ .reg .u64 t; cvta.to.shared.u64 t, %1; cvt.u32.u64 %0, t; }"
        : "=r"(a) : "l"(p));
    return a;
}

__device__ __forceinline__ uint32_t pack_bf2(__nv_bfloat16 a, __nv_bfloat16 b) {
    return (uint32_t)__bfloat16_as_ushort(a) |
           ((uint32_t)__bfloat16_as_ushort(b) << 16);
}

__device__ __forceinline__ void split4(const float4 f, uint2& hi, uint2& lo) {
    __nv_bfloat16 h0 = __float2bfloat16_rn(f.x);
    __nv_bfloat16 h1 = __float2bfloat16_rn(f.y);
    __nv_bfloat16 h2 = __float2bfloat16_rn(f.z);
    __nv_bfloat16 h3 = __float2bfloat16_rn(f.w);
    __nv_bfloat16 l0 = __float2bfloat16_rn(f.x - __bfloat162float(h0));
    __nv_bfloat16 l1 = __float2bfloat16_rn(f.y - __bfloat162float(h1));
    __nv_bfloat16 l2 = __float2bfloat16_rn(f.z - __bfloat162float(h2));
    __nv_bfloat16 l3 = __float2bfloat16_rn(f.w - __bfloat162float(h3));
    hi.x = pack_bf2(h0, h1); hi.y = pack_bf2(h2, h3);
    lo.x = pack_bf2(l0, l1); lo.y = pack_bf2(l2, l3);
}

#define RS2 48
#define NS 4
#define ST_AHI 0
#define ST_ALO 6144
#define ST_BHI 12288
#define ST_BLO 18432
#define ST_BYTES 24576
#define DSMEM_V6 (NS * ST_BYTES)   // 98304

// ---------------------------------------------------------------------------
// MmaB16v6: 128x128 tile, 128 threads (4 warps, 64x64 warp tile),
// K-chunk 16, 4-stage cp.async pipeline, 2 CTAs/SM, natural regs (~207).
// MMA:LDSM = 6:1 per warp. Term-ordered MMAs for distance-32 RAW chains.
// ---------------------------------------------------------------------------
struct MmaB16v6 {
    float acc[4][8][4];

    __device__ __forceinline__ static void issue(
        uint32_t sb,
        const __nv_bfloat16* Ah, const __nv_bfloat16* Al, size_t sA,
        const __nv_bfloat16* Bh, const __nv_bfloat16* Bl, size_t sB,
        int k0, int tid)
    {
        const int r0   = tid >> 1;          // 0..63
        const int half = tid & 1;
        #pragma unroll
        for (int p = 0; p < 2; p++) {
            const int r = r0 + p * 64;
            const uint32_t so = (uint32_t)r * RS2 + half * 16;
            const size_t oA = (size_t)r * sA + k0 + half * 8;
            const size_t oB = (size_t)r * sB + k0 + half * 8;
            CP16(sb + ST_AHI + so, Ah + oA);
            CP16(sb + ST_ALO + so, Al + oA);
            CP16(sb + ST_BHI + so, Bh + oB);
            CP16(sb + ST_BLO + so, Bl + oB);
        }
    }

    __device__ __forceinline__ void run(
        uint32_t sbase,
        const __nv_bfloat16* Ah, const __nv_bfloat16* Al, size_t sA,
        const __nv_bfloat16* Bh, const __nv_bfloat16* Bl, size_t sB,
        const int nIter, const int tid)
    {
        const int lane = tid & 31;
        const int wid  = tid >> 5;          // 0..3
        const int wm   = wid >> 1;          // 0..1 (64-row band)
        const int wn   = wid & 1;           // 0..1 (64-col band)

        #pragma unroll
        for (int i = 0; i < 4; i++)
            #pragma unroll
            for (int j = 0; j < 8; j++)
                #pragma unroll
                for (int c = 0; c < 4; c++) acc[i][j][c] = 0.0f;

        const uint32_t aAddr = sbase + ST_AHI
            + (uint32_t)(wm * 64 + (lane & 15)) * RS2 + (lane >> 4) * 16;
        const uint32_t bAddr = sbase + ST_BHI
            + (uint32_t)(wn * 64 + (lane & 7) + ((lane >> 4) & 1) * 8) * RS2
            + ((lane >> 3) & 1) * 16;

        #pragma unroll
        for (int p = 0; p < NS - 1; p++) {
            if (p < nIter)
                issue(sbase + p * ST_BYTES, Ah, Al, sA, Bh, Bl, sB, p * 16, tid);
            CPCOMMIT();
        }

        for (int s = 0; s < nIter; s++) {
            CPWAIT2();
            __syncthreads();

            const uint32_t bo = (uint32_t)(s & (NS - 1)) * ST_BYTES;
            uint32_t ahi[4][4], alo[4][4];
            uint32_t bhi[4][4], blo[4][4];
            #pragma unroll
            for (int mt = 0; mt < 4; mt++) {
                const uint32_t a = aAddr + bo + mt * (16 * RS2);
                LDSM_X4(ahi[mt][0], ahi[mt][1], ahi[mt][2], ahi[mt][3], a);
                LDSM_X4(alo[mt][0], alo[mt][1], alo[mt][2], alo[mt][3],
                        a + (ST_ALO - ST_AHI));
            }
            #pragma unroll
            for (int nq = 0; nq < 4; nq++) {
                const uint32_t b = bAddr + bo + nq * (16 * RS2);
                LDSM_X4(bhi[nq][0], bhi[nq][1], bhi[nq][2], bhi[nq][3], b);
                LDSM_X4(blo[nq][0], blo[nq][1], blo[nq][2], blo[nq][3],
                        b + (ST_BLO - ST_BHI));
            }
            // term-ordered: all hi*hi, then hi*lo, then lo*hi (max ILP)
            #pragma unroll
            for (int mt = 0; mt < 4; mt++)
                #pragma unroll
                for (int nq = 0; nq < 4; nq++)
                    #pragma unroll
                    for (int t = 0; t < 2; t++)
                        MMA16816(acc[mt][nq * 2 + t],
                                 ahi[mt][0], ahi[mt][1], ahi[mt][2], ahi[mt][3],
                                 bhi[nq][t * 2], bhi[nq][t * 2 + 1]);
            #pragma unroll
            for (int mt = 0; mt < 4; mt++)
                #pragma unroll
                for (int nq = 0; nq < 4; nq++)
                    #pragma unroll
                    for (int t = 0; t < 2; t++)
                        MMA16816(acc[mt][nq * 2 + t],
                                 ahi[mt][0], ahi[mt][1], ahi[mt][2], ahi[mt][3],
                                 blo[nq][t * 2], blo[nq][t * 2 + 1]);
            #pragma unroll
            for (int mt = 0; mt < 4; mt++)
                #pragma unroll
                for (int nq = 0; nq < 4; nq++)
                    #pragma unroll
                    for (int t = 0; t < 2; t++)
                        MMA16816(acc[mt][nq * 2 + t],
                                 alo[mt][0], alo[mt][1], alo[mt][2], alo[mt][3],
                                 bhi[nq][t * 2], bhi[nq][t * 2 + 1]);

            const int nx = s + NS - 1;
            if (nx < nIter)
                issue(sbase + (uint32_t)(nx & (NS - 1)) * ST_BYTES,
                      Ah, Al, sA, Bh, Bl, sB, nx * 16, tid);
            CPCOMMIT();
        }
        __syncthreads();
    }
};

// ---------------------------------------------------------------------------
// Split fp32 tensors into bf16 hi/lo planes
// ---------------------------------------------------------------------------
__global__ __launch_bounds__(256) void split_inputs(
    const float* __restrict__ a0, const float* __restrict__ a1,
    const float* __restrict__ a2,
    __nv_bfloat16* __restrict__ h0, __nv_bfloat16* __restrict__ l0,
    __nv_bfloat16* __restrict__ h1, __nv_bfloat16* __restrict__ l1,
    __nv_bfloat16* __restrict__ h2, __nv_bfloat16* __restrict__ l2)
{
    const int z = blockIdx.y;
    const float* s = (z == 0) ? a0 : (z == 1) ? a1 : a2;
    __nv_bfloat16* H = (z == 0) ? h0 : (z == 1) ? h1 : h2;
    __nv_bfloat16* L = (z == 0) ? l0 : (z == 1) ? l1 : l2;
    const size_t i = ((size_t)blockIdx.x * 256 + threadIdx.x) * 4;
    float4 f = *(const float4*)(s + i);
    uint2 hi, lo;
    split4(f, hi, lo);
    *(uint2*)(H + i) = hi;
    *(uint2*)(L + i) = lo;
}

__global__ __launch_bounds__(256) void split_weights(
    const float* __restrict__ w0, const float* __restrict__ w1,
    const float* __restrict__ w2, const float* __restrict__ w3,
    __nv_bfloat16* __restrict__ wh, __nv_bfloat16* __restrict__ wl)
{
    const int z = blockIdx.y;
    const float* s = (z == 0) ? w0 : (z == 1) ? w1 : (z == 2) ? w2 : w3;
    const size_t base = (size_t)z * DD * DD;
    const size_t i = ((size_t)blockIdx.x * 256 + threadIdx.x) * 4;
    float4 f = *(const float4*)(s + i);
    uint2 hi, lo;
    split4(f, hi, lo);
    *(uint2*)(wh + base + i) = hi;
    *(uint2*)(wl + base + i) = lo;
}

// ---------------------------------------------------------------------------
// Batched Q/K/V projection (v6 core, 128 threads)
// ---------------------------------------------------------------------------
__global__ void proj_qkv(
    const __nv_bfloat16* __restrict__ qih, const __nv_bfloat16* __restrict__ qil,
    const __nv_bfloat16* __restrict__ kih, const __nv_bfloat16* __restrict__ kil,
    const __nv_bfloat16* __restrict__ vih, const __nv_bfloat16* __restrict__ vil,
    const __nv_bfloat16* __restrict__ wh, const __nv_bfloat16* __restrict__ wl,
    const float* __restrict__ bq, const float* __restrict__ bk,
    const float* __restrict__ bv,
    __nv_bfloat16* __restrict__ qh, __nv_bfloat16* __restrict__ ql,
    __nv_bfloat16* __restrict__ kh, __nv_bfloat16* __restrict__ kl,
    float* __restrict__ v)
{
    extern __shared__ char dsm[];
    const uint32_t sbase = smem_u32(dsm);
    const int tid  = threadIdx.x;
    const int lane = tid & 31;
    const int wid  = tid >> 5;
    const int wm   = wid >> 1;
    const int wn   = wid & 1;
    const int bn   = blockIdx.x;
    const int bm   = blockIdx.y;
    const int z    = blockIdx.z;

    const __nv_bfloat16* Ah = (z == 0) ? qih : (z == 1) ? kih : vih;
    const __nv_bfloat16* Al = (z == 0) ? qil : (z == 1) ? kil : vil;
    const float* bias = (z == 0) ? bq : (z == 1) ? bk : bv;
    const size_t wbase = (size_t)z * DD * DD;

    MmaB16v6 core;
    core.run(sbase,
             Ah + (size_t)(bm * 128) * DD, Al + (size_t)(bm * 128) * DD, DD,
             wh + wbase + (size_t)(bn * 128) * DD,
             wl + wbase + (size_t)(bn * 128) * DD, DD,
             DD / 16, tid);

    #pragma unroll
    for (int mt = 0; mt < 4; mt++) {
        const int row = bm * 128 + wm * 64 + mt * 16 + (lane >> 2);
        #pragma unroll
        for (int nt = 0; nt < 8; nt++) {
            const int col = bn * 128 + wn * 64 + nt * 8 + (lane & 3) * 2;
            const float b0 = bias[col], b1 = bias[col + 1];
            const float v0 = core.acc[mt][nt][0] + b0;
            const float v1 = core.acc[mt][nt][1] + b1;
            const float v2 = core.acc[mt][nt][2] + b0;
            const float v3 = core.acc[mt][nt][3] + b1;
            if (z == 2) {
                *(float2*)(v + (size_t)row * DD + col) = make_float2(v0, v1);
                *(float2*)(v + (size_t)(row + 8) * DD + col) = make_float2(v2, v3);
            } else {
                __nv_bfloat16* H = (z == 0) ? qh : kh;
                __nv_bfloat16* L = (z == 0) ? ql : kl;
                __nv_bfloat16 h0 = __float2bfloat16_rn(v0);
                __nv_bfloat16 h1 = __float2bfloat16_rn(v1);
                __nv_bfloat16 h2 = __float2bfloat16_rn(v2);
                __nv_bfloat16 h3 = __float2bfloat16_rn(v3);
                *(uint32_t*)(H + (size_t)row * DD + col) = pack_bf2(h0, h1);
                *(uint32_t*)(L + (size_t)row * DD + col) = pack_bf2(
                    __float2bfloat16_rn(v0 - __bfloat162float(h0)),
                    __float2bfloat16_rn(v1 - __bfloat162float(h1)));
                *(uint32_t*)(H + (size_t)(row + 8) * DD + col) = pack_bf2(h2, h3);
                *(uint32_t*)(L + (size_t)(row + 8) * DD + col) = pack_bf2(
                    __float2bfloat16_rn(v2 - __bfloat162float(h2)),
                    __float2bfloat16_rn(v3 - __bfloat162float(h3)));
            }
        }
    }
}

// ---------------------------------------------------------------------------
// Final GEMM (v6 core): out = x @ Wo^T + bo
// ---------------------------------------------------------------------------
__global__ void gemm_b16(
    const __nv_bfloat16* __restrict__ Ah, const __nv_bfloat16* __restrict__ Al,
    const __nv_bfloat16* __restrict__ Wh, const __nv_bfloat16* __restrict__ Wl,
    const float* __restrict__ bias, float* __restrict__ C)
{
    extern __shared__ char dsm[];
    const uint32_t sbase = smem_u32(dsm);
    const int tid  = threadIdx.x;
    const int lane = tid & 31;
    const int wid  = tid >> 5;
    const int wm   = wid >> 1;
    const int wn   = wid & 1;
    const int bn   = blockIdx.x;
    const int bm   = blockIdx.y;

    MmaB16v6 core;
    core.run(sbase,
             Ah + (size_t)(bm * 128) * DD, Al + (size_t)(bm * 128) * DD, DD,
             Wh + (size_t)(bn * 128) * DD, Wl + (size_t)(bn * 128) * DD, DD,
             DD / 16, tid);

    #pragma unroll
    for (int mt = 0; mt < 4; mt++) {
        const int row = bm * 128 + wm * 64 + mt * 16 + (lane >> 2);
        #pragma unroll
        for (int nt = 0; nt < 8; nt++) {
            const int col = bn * 128 + wn * 64 + nt * 8 + (lane & 3) * 2;
            const float b0 = bias[col], b1 = bias[col + 1];
            float2 o0, o1;
            o0.x = core.acc[mt][nt][0] + b0; o0.y = core.acc[mt][nt][1] + b1;
            o1.x = core.acc[mt][nt][2] + b0; o1.y = core.acc[mt][nt][3] + b1;
            *(float2*)(C + (size_t)row * DD + col) = o0;
            *(float2*)(C + (size_t)(row + 8) * DD + col) = o1;
        }
    }
}

// ---------------------------------------------------------------------------
// Scores+exp (v6 core): triangular grid; E planes + row-sum partials.
// ---------------------------------------------------------------------------
__global__ void scores_exp_kernel(
    const __nv_bfloat16* __restrict__ qh, const __nv_bfloat16* __restrict__ ql,
    const __nv_bfloat16* __restrict__ kh, const __nv_bfloat16* __restrict__ kl,
    __nv_bfloat16* __restrict__ eh, __nv_bfloat16* __restrict__ el,
    float* __restrict__ rpart)
{
    const int idx = blockIdx.x;            // 0..135 (lower-triangle tile id)
    int bm = (int)((sqrtf(8.f * idx + 1.f) - 1.f) * 0.5f);
    while ((bm + 1) * (bm + 2) / 2 <= idx) bm++;
    while (bm * (bm + 1) / 2 > idx) bm--;
    const int bn = idx - bm * (bm + 1) / 2;
    const int bh = blockIdx.y;
    const int tid = threadIdx.x;

    extern __shared__ char dsm[];
    __shared__ float rs[128][2];
    const uint32_t sbase = smem_u32(dsm);
    const int lane = tid & 31;
    const int wid  = tid >> 5;
    const int wm   = wid >> 1;
    const int wn   = wid & 1;
    const int b = bh / HH, h = bh % HH;

    const size_t aoff = (size_t)(b * SS + bm * 128) * DD + h * DK;
    const size_t boff = (size_t)(b * SS + bn * 128) * DD + h * DK;

    MmaB16v6 core;
    core.run(sbase, qh + aoff, ql + aoff, DD, kh + boff, kl + boff, DD,
             DK / 16, tid);

    __nv_bfloat16* peh = eh + (size_t)bh * SS * SS;
    __nv_bfloat16* pel = el + (size_t)bh * SS * SS;

    float rsum[4][2];
    #pragma unroll
    for (int mt = 0; mt < 4; mt++) { rsum[mt][0] = 0.f; rsum[mt][1] = 0.f; }

    #pragma unroll
    for (int mt = 0; mt < 4; mt++) {
        const int r0 = bm * 128 + wm * 64 + mt * 16 + (lane >> 2);
        const int r1 = r0 + 8;
        #pragma unroll
        for (int nt = 0; nt < 8; nt++) {
            const int col = bn * 128 + wn * 64 + nt * 8 + (lane & 3) * 2;
            float e0 = (col     <= r0) ? __expf(core.acc[mt][nt][0] * SCALE) : 0.f;
            float e1 = (col + 1 <= r0) ? __expf(core.acc[mt][nt][1] * SCALE) : 0.f;
            float e2 = (col     <= r1) ? __expf(core.acc[mt][nt][2] * SCALE) : 0.f;
            float e3 = (col + 1 <= r1) ? __expf(core.acc[mt][nt][3] * SCALE) : 0.f;
            rsum[mt][0] += e0 + e1;
            rsum[mt][1] += e2 + e3;
            __nv_bfloat16 h0 = __float2bfloat16_rn(e0);
            __nv_bfloat16 h1 = __float2bfloat16_rn(e1);
            __nv_bfloat16 h2 = __float2bfloat16_rn(e2);
            __nv_bfloat16 h3 = __float2bfloat16_rn(e3);
            *(uint32_t*)(peh + (size_t)r0 * SS + col) = pack_bf2(h0, h1);
            *(uint32_t*)(pel + (size_t)r0 * SS + col) = pack_bf2(
                __float2bfloat16_rn(e0 - __bfloat162float(h0)),
                __float2bfloat16_rn(e1 - __bfloat162float(h1)));
            *(uint32_t*)(peh + (size_t)r1 * SS + col) = pack_bf2(h2, h3);
            *(uint32_t*)(pel + (size_t)r1 * SS + col) = pack_bf2(
                __float2bfloat16_rn(e2 - __bfloat162float(h2)),
                __float2bfloat16_rn(e3 - __bfloat162float(h3)));
        }
    }

    #pragma unroll
    for (int mt = 0; mt < 4; mt++) {
        #pragma unroll
        for (int hf = 0; hf < 2; hf++) {
            float vv = rsum[mt][hf];
            vv += __shfl_xor_sync(0xffffffffu, vv, 1);
            vv += __shfl_xor_sync(0xffffffffu, vv, 2);
            if ((lane & 3) == 0) {
                const int lrow = wm * 64 + mt * 16 + hf * 8 + (lane >> 2);
                rs[lrow][wn] = vv;
            }
        }
    }
    __syncthreads();
    const float p = rs[tid][0] + rs[tid][1];
    rpart[((size_t)bh * SS + bm * 128 + tid) * 16 + bn] = p;
}

// ---------------------------------------------------------------------------
// ginv: 1/rowsum from partials
// ---------------------------------------------------------------------------
__global__ __launch_bounds__(256) void ginv_kernel(
    const float* __restrict__ rpart, float* __restrict__ ginv)
{
    const int i = blockIdx.x * 256 + threadIdx.x;   // bh*SS + s
    const int s = i & (SS - 1);
    const float* p = rpart + (size_t)i * 16;
    const int nb = (s >> 7) + 1;
    float sum = 0.f;
    for (int k = 0; k < nb; k++) sum += p[k];
    ginv[i] = 1.0f / sum;
}

// ---------------------------------------------------------------------------
// Zero the above-diagonal tail of attn (side stream)
// ---------------------------------------------------------------------------
__global__ __launch_bounds__(256) void zero_tail(float* __restrict__ attn)
{
    const int blk = blockIdx.x;           // bh*SS + s
    const int s   = blk & (SS - 1);
    const int limit = ((s >> 7) + 1) * 128;
    float* row = attn + (size_t)blk * SS;
    const float4 z = make_float4(0.f, 0.f, 0.f, 0.f);
    for (int j = limit + threadIdx.x * 4; j < SS; j += 1024)
        *(float4*)(row + j) = z;
}

// ---------------------------------------------------------------------------
// Finalize (prefix only): attn[0..limit) = (Eh+El)*inv. Tail pre-zeroed.
// ---------------------------------------------------------------------------
__global__ __launch_bounds__(256) void finalize_prefix(
    const __nv_bfloat16* __restrict__ eh, const __nv_bfloat16* __restrict__ el,
    const float* __restrict__ ginv, float* __restrict__ attn)
{
    const int blk = blockIdx.x;           // bh*SS + s
    const int s   = blk & (SS - 1);
    const float inv = ginv[blk];
    const __nv_bfloat16* reh = eh + (size_t)blk * SS;
    const __nv_bfloat16* rel = el + (size_t)blk * SS;
    float* row = attn + (size_t)blk * SS;
    const int limit = ((s >> 7) + 1) * 128;
    for (int j = threadIdx.x * 4; j < limit; j += 1024) {
        const __nv_bfloat162 h2 = *(const __nv_bfloat162*)(reh + j);
        const __nv_bfloat162 h3 = *(const __nv_bfloat162*)(reh + j + 2);
        const __nv_bfloat162 l2 = *(const __nv_bfloat162*)(rel + j);
        const __nv_bfloat162 l3 = *(const __nv_bfloat162*)(rel + j + 2);
        float4 o;
        o.x = (__bfloat162float(h2.x) + __bfloat162float(l2.x)) * inv;
        o.y = (__bfloat162float(h2.y) + __bfloat162float(l2.y)) * inv;
        o.z = (__bfloat162float(h3.x) + __bfloat162float(l3.x)) * inv;
        o.w = (__bfloat162float(h3.y) + __bfloat162float(l3.y)) * inv;
        *(float4*)(row + j) = o;
    }
}

// ---------------------------------------------------------------------------
// Transpose V per head into bf16 hi/lo planes: vt[bh][d][s]
// ---------------------------------------------------------------------------
__global__ __launch_bounds__(256) void transpose_v(
    const float* __restrict__ v,
    __nv_bfloat16* __restrict__ vth, __nv_bfloat16* __restrict__ vtl)
{
    __shared__ float t[32][33];
    const int bh = blockIdx.z, b = bh / HH, h = bh % HH;
    const int s0 = blockIdx.x * 32, d0 = blockIdx.y * 32;
    const int tx = threadIdx.x & 31, ty = threadIdx.x >> 5;
    #pragma unroll
    for (int i = 0; i < 4; i++)
        t[ty + i * 8][tx] =
            v[(size_t)(b * SS + s0 + ty + i * 8) * DD + h * DK + d0 + tx];
    __syncthreads();
    #pragma unroll
    for (int i = 0; i < 4; i++) {
        const float f = t[tx][ty + i * 8];
        const __nv_bfloat16 hh = __float2bfloat16_rn(f);
        const __nv_bfloat16 ll = __float2bfloat16_rn(f - __bfloat162float(hh));
        const size_t idx = (size_t)bh * DK * SS + (size_t)(d0 + ty + i * 8) * SS
                         + s0 + tx;
        vth[idx] = hh;
        vtl[idx] = ll;
    }
}

// ---------------------------------------------------------------------------
// AV (v6 core): x = (E @ V) * inv; heavy-first 1D grid.
// ---------------------------------------------------------------------------
__global__ void av_mma_kernel(
    const __nv_bfloat16* __restrict__ eh, const __nv_bfloat16* __restrict__ el,
    const __nv_bfloat16* __restrict__ vth, const __nv_bfloat16* __restrict__ vtl,
    const float* __restrict__ ginv,
    __nv_bfloat16* __restrict__ xh, __nv_bfloat16* __restrict__ xl)
{
    const int t = blockIdx.x;              // 0..511, heavy bm first
    const int bm = 15 - (t >> 5);
    const int bh = t & 31;
    extern __shared__ char dsm[];
    const uint32_t sbase = smem_u32(dsm);
    const int b = bh / HH, h = bh % HH;
    const int tid  = threadIdx.x;
    const int lane = tid & 31;
    const int wid  = tid >> 5;
    const int wm   = wid >> 1;
    const int wn   = wid & 1;

    const size_t aoff = (size_t)bh * SS * SS + (size_t)(bm * 128) * SS;
    const size_t boff = (size_t)bh * DK * SS;

    MmaB16v6 core;
    core.run(sbase, eh + aoff, el + aoff, SS, vth + boff, vtl + boff, SS,
             (bm + 1) * 8, tid);

    #pragma unroll
    for (int mt = 0; mt < 4; mt++) {
        const int row = bm * 128 + wm * 64 + mt * 16 + (lane >> 2);
        const float inv0 = ginv[(size_t)bh * SS + row];
        const float inv1 = ginv[(size_t)bh * SS + row + 8];
        #pragma unroll
        for (int nt = 0; nt < 8; nt++) {
            const int col = wn * 64 + nt * 8 + (lane & 3) * 2;
            const float v0 = core.acc[mt][nt][0] * inv0;
            const float v1 = core.acc[mt][nt][1] * inv0;
            const float v2 = core.acc[mt][nt][2] * inv1;
            const float v3 = core.acc[mt][nt][3] * inv1;
            __nv_bfloat16 h0 = __float2bfloat16_rn(v0);
            __nv_bfloat16 h1 = __float2bfloat16_rn(v1);
            __nv_bfloat16 h2 = __float2bfloat16_rn(v2);
            __nv_bfloat16 h3 = __float2bfloat16_rn(v3);
            const size_t o0 = (size_t)(b * SS + row) * DD + h * DK + col;
            const size_t o1 = (size_t)(b * SS + row + 8) * DD + h * DK + col;
            *(uint32_t*)(xh + o0) = pack_bf2(h0, h1);
            *(uint32_t*)(xl + o0) = pack_bf2(
                __float2bfloat16_rn(v0 - __bfloat162float(h0)),
                __float2bfloat16_rn(v1 - __bfloat162float(h1)));
            *(uint32_t*)(xh + o1) = pack_bf2(h2, h3);
            *(uint32_t*)(xl + o1) = pack_bf2(
                __float2bfloat16_rn(v2 - __bfloat162float(h2)),
                __float2bfloat16_rn(v3 - __bfloat162float(h3)));
        }
    }
}

// ---------------------------------------------------------------------------
extern "C" void kernel_launch(void* const* d_in, const int* in_sizes, int n_in,
                              void* d_out, int out_size)
{
    const float* query = (const float*)d_in[0];
    const float* key   = (const float*)d_in[1];
    const float* value = (const float*)d_in[2];
    const float* Wq = (const float*)d_in[3];
    const float* bq = (const float*)d_in[4];
    const float* Wk = (const float*)d_in[5];
    const float* bk = (const float*)d_in[6];
    const float* Wv = (const float*)d_in[7];
    const float* bv = (const float*)d_in[8];
    const float* Wo = (const float*)d_in[9];
    const float* bo = (const float*)d_in[10];

    float* out  = (float*)d_out;                       // [4096, 2048]
    float* attn = out + (size_t)MTOK * DD;             // [32, 2048, 2048]

    float *v, *rpart, *ginv;
    __nv_bfloat16 *qih, *qil, *kih, *kil, *vih, *vil, *wh, *wl;
    __nv_bfloat16 *qh, *ql, *kh, *kl, *xh, *xl, *vth, *vtl, *eh, *el;
    cudaGetSymbolAddress((void**)&v, g_v);
    cudaGetSymbolAddress((void**)&rpart, g_rpart);
    cudaGetSymbolAddress((void**)&ginv, g_inv);
    cudaGetSymbolAddress((void**)&qih, g_qih);
    cudaGetSymbolAddress((void**)&qil, g_qil);
    cudaGetSymbolAddress((void**)&kih, g_kih);
    cudaGetSymbolAddress((void**)&kil, g_kil);
    cudaGetSymbolAddress((void**)&vih, g_vih);
    cudaGetSymbolAddress((void**)&vil, g_vil);
    cudaGetSymbolAddress((void**)&wh, g_wh);
    cudaGetSymbolAddress((void**)&wl, g_wl);
    cudaGetSymbolAddress((void**)&qh, g_qh);
    cudaGetSymbolAddress((void**)&ql, g_ql);
    cudaGetSymbolAddress((void**)&kh, g_kh);
    cudaGetSymbolAddress((void**)&kl, g_kl);
    cudaGetSymbolAddress((void**)&xh, g_xh);
    cudaGetSymbolAddress((void**)&xl, g_xl);
    cudaGetSymbolAddress((void**)&vth, g_vth);
    cudaGetSymbolAddress((void**)&vtl, g_vtl);
    cudaGetSymbolAddress((void**)&eh, g_eh);
    cudaGetSymbolAddress((void**)&el, g_el);

    static cudaStream_t s1 = nullptr;
    static cudaEvent_t evA = nullptr, evB = nullptr, evF = nullptr;
    if (s1 == nullptr) {
        cudaStreamCreateWithFlags(&s1, cudaStreamNonBlocking);
        cudaEventCreateWithFlags(&evA, cudaEventDisableTiming);
        cudaEventCreateWithFlags(&evB, cudaEventDisableTiming);
        cudaEventCreateWithFlags(&evF, cudaEventDisableTiming);
        cudaFuncSetAttribute(proj_qkv,
            cudaFuncAttributeMaxDynamicSharedMemorySize, DSMEM_V6);
        cudaFuncSetAttribute(gemm_b16,
            cudaFuncAttributeMaxDynamicSharedMemorySize, DSMEM_V6);
        cudaFuncSetAttribute(scores_exp_kernel,
            cudaFuncAttributeMaxDynamicSharedMemorySize, DSMEM_V6);
        cudaFuncSetAttribute(av_mma_kernel,
            cudaFuncAttributeMaxDynamicSharedMemorySize, DSMEM_V6);
    }

    // Fork side stream: zero the above-diagonal attn tail (no dependencies)
    cudaEventRecord(evA, 0);
    cudaStreamWaitEvent(s1, evA, 0);
    zero_tail<<<BB * HH * SS, 256, 0, s1>>>(attn);

    // Main stream: splits -> proj -> transpose -> scores -> ginv
    dim3 gsi((MTOK * DD) / (256 * 4), 3);
    split_inputs<<<gsi, 256>>>(query, key, value,
                               qih, qil, kih, kil, vih, vil);
    dim3 gsw((DD * DD) / (256 * 4), 4);
    split_weights<<<gsw, 256>>>(Wq, Wk, Wv, Wo, wh, wl);

    dim3 gproj(DD / 128, MTOK / 128, 3);                // (16, 32, 3)
    proj_qkv<<<gproj, 128, DSMEM_V6>>>(
        qih, qil, kih, kil, vih, vil, wh, wl, bq, bk, bv,
        qh, ql, kh, kl, v);

    dim3 gtr(SS / 32, DK / 32, BB * HH);
    transpose_v<<<gtr, 256>>>(v, vth, vtl);

    dim3 gsc(136, BB * HH);
    scores_exp_kernel<<<gsc, 128, DSMEM_V6>>>(qh, ql, kh, kl, eh, el, rpart);

    ginv_kernel<<<(BB * HH * SS) / 256, 256>>>(rpart, ginv);

    // Side stream: finalize attn prefix (overlaps AV + output projection)
    cudaEventRecord(evB, 0);
    cudaStreamWaitEvent(s1, evB, 0);
    finalize_prefix<<<BB * HH * SS, 256, 0, s1>>>(eh, el, ginv, attn);
    cudaEventRecord(evF, s1);

    // Main stream: AV, output projection
    av_mma_kernel<<<512, 128, DSMEM_V6>>>(eh, el, vth, vtl, ginv, xh, xl);

    dim3 gout(DD / 128, MTOK / 128);                    // (16, 32)
    gemm_b16<<<gout, 128, DSMEM_V6>>>(
        xh, xl, wh + (size_t)3 * DD * DD, wl + (size_t)3 * DD * DD, bo, out);

    // Join side stream into the graph
    cudaStreamWaitEvent(0, evF, 0);
}